// round 4
// baseline (speedup 1.0000x reference)
#include <cuda_runtime.h>
#include <math.h>
#include <stdint.h>

// Problem dims (fixed by reference setup_inputs)
#define BATCH 8
#define SQ    2048
#define SKV   2048
#define HID   1024

// Scratch (allocation-free rule: __device__ globals)
__device__ float g_Q[(size_t)BATCH * SQ  * HID];   // 64 MB
__device__ float g_K[(size_t)BATCH * SKV * HID];   // 64 MB
__device__ float g_V[(size_t)BATCH * SKV * HID];   // 64 MB
__device__ float g_S[(size_t)BATCH * SQ  * SKV];   // 128 MB

// ---------------------------------------------------------------------------
// tf32 helpers
// ---------------------------------------------------------------------------
__device__ __forceinline__ uint32_t f2tf32(float f) {
    uint32_t r;
    asm("cvt.rna.tf32.f32 %0, %1;" : "=r"(r) : "f"(f));
    return r;
}

__device__ __forceinline__ void mma_tf32(float* d, const uint32_t* a, const uint32_t* b) {
    asm volatile(
        "mma.sync.aligned.m16n8k8.row.col.f32.tf32.tf32.f32 "
        "{%0,%1,%2,%3}, {%4,%5,%6,%7}, {%8,%9}, {%0,%1,%2,%3};"
        : "+f"(d[0]), "+f"(d[1]), "+f"(d[2]), "+f"(d[3])
        : "r"(a[0]), "r"(a[1]), "r"(a[2]), "r"(a[3]),
          "r"(b[0]), "r"(b[1]));
}

// ---------------------------------------------------------------------------
// 3xTF32 tensor-core GEMM: C[M,N] = A[M,K] * B (+epilogue), fp32 in/out.
//   BT=false: B is [K,N] row-major (NN)
//   BT=true : B is [N,K] row-major (NT: C = A * B^T)
// EPI: 0 plain | 1 +bias[n] | 2 scores: c*scale + (1-mask[bz*N+n])*(-1e4)
// Block 128x128, BK=16, 256 threads = 8 warps (2x4), warp tile 64x32.
// Operands split hi/lo (tf32); acc = ah*bh + ah*bl + al*bh (fp32 accum).
//
// Smem holds tiles in *fragment-packed* order so compute uses vector LDS:
//  A element (m,k), m in 0..127, k in 0..15:
//    blk  = (m>>4)*2 + (k>>3)            (16 blocks of 16m x 8k)
//    lane = (m&7)*4 + (k&3)
//    reg  = ((k>>2)&1)*2 + ((m>>3)&1)    (mma a-frag reg index)
//    off  = blk*128 + lane*4 + reg       -> one LDS.128 per A fragment
//  B element (n,k), n in 0..127, k in 0..15:
//    blk  = (n>>3)*2 + (k>>3)            (32 blocks of 8n x 8k)
//    lane = (n&7)*4 + (k&3)
//    reg  = (k>>2)&1
//    off  = blk*64 + lane*2 + reg        -> one LDS.64 per B fragment
// Double buffered; 4 arrays (Ah, Al, Bh, Bl) of [2][2048] floats = 64 KB.
// Requires M%128==0, N%128==0, K%16==0 (true for all shapes here).
// ---------------------------------------------------------------------------
#define TILE_WORDS 2048
#define SMEM_WORDS (4 * 2 * TILE_WORDS)
#define SMEM_BYTES (SMEM_WORDS * 4)      // 65536

__device__ __forceinline__ int aoff(int m, int k) {
    return ((m >> 4) << 8) + ((k >> 3) << 7)
         + ((m & 7) << 4) + ((k & 3) << 2)
         + (((k >> 2) & 1) << 1) + ((m >> 3) & 1);
}
__device__ __forceinline__ int boff(int n, int k) {
    return ((n >> 3) << 7) + ((k >> 3) << 6)
         + ((n & 7) << 3) + ((k & 3) << 1)
         + ((k >> 2) & 1);
}

template<bool BT, int EPI>
__global__ __launch_bounds__(256)
void gemm_kern(const float* __restrict__ A, const float* __restrict__ Bm,
               const float* __restrict__ E, float* __restrict__ C,
               int M, int N, int K,
               size_t sA, size_t sB, size_t sC, float scale)
{
    extern __shared__ uint32_t smem[];
    uint32_t* const Ah = smem;                        // [2][2048]
    uint32_t* const Al = Ah + 2 * TILE_WORDS;
    uint32_t* const Bh = Al + 2 * TILE_WORDS;
    uint32_t* const Bl = Bh + 2 * TILE_WORDS;

    const int bz = blockIdx.z;
    const float* Ab = A  + (size_t)bz * sA;
    const float* Bb = Bm + (size_t)bz * sB;
    float*       Cb = C  + (size_t)bz * sC;

    const int bm = blockIdx.y * 128;
    const int bn = blockIdx.x * 128;
    const int tid  = threadIdx.x;
    const int wid  = tid >> 5;
    const int lane = tid & 31;
    const int g  = lane >> 2;         // group id (0..7)
    const int tg = lane & 3;          // thread-in-group (0..3)
    const int wm = (wid >> 2) * 64;   // warp m offset in block tile
    const int wn = (wid & 3) * 32;    // warp n offset

    // ---- global->smem staging slots (2 float4 of A, 2 of B per thread) ----
    const int aslot0 = tid, aslot1 = tid + 256;
    const int ar0 = aslot0 >> 2, ak0 = aslot0 & 3;   // A / BT-B: row, k-quad
    const int ar1 = aslot1 >> 2, ak1 = aslot1 & 3;
    const int kr0 = aslot0 >> 5, cq0 = aslot0 & 31;  // NN-B: k-row, n-quad
    const int kr1 = aslot1 >> 5, cq1 = aslot1 & 31;

    float4 fa0, fa1, fb0, fb1;

    auto fetchA = [&](int k0) {
        fa0 = *reinterpret_cast<const float4*>(Ab + (size_t)(bm + ar0) * K + k0 + ak0 * 4);
        fa1 = *reinterpret_cast<const float4*>(Ab + (size_t)(bm + ar1) * K + k0 + ak1 * 4);
    };
    auto fetchB = [&](int k0) {
        if (BT) {
            fb0 = *reinterpret_cast<const float4*>(Bb + (size_t)(bn + ar0) * K + k0 + ak0 * 4);
            fb1 = *reinterpret_cast<const float4*>(Bb + (size_t)(bn + ar1) * K + k0 + ak1 * 4);
        } else {
            fb0 = *reinterpret_cast<const float4*>(Bb + (size_t)(k0 + kr0) * N + bn + cq0 * 4);
            fb1 = *reinterpret_cast<const float4*>(Bb + (size_t)(k0 + kr1) * N + bn + cq1 * 4);
        }
    };

    auto split1 = [&](float f, uint32_t& hi, uint32_t& lo) {
        hi = f2tf32(f);
        lo = f2tf32(f - __uint_as_float(hi));
    };

    // Store one float4 of A-type data (fixed row, 4 consecutive k) fragment-packed.
    auto storeAquad = [&](uint32_t* Hb, uint32_t* Lb, int row, int kq, float4 v) {
        uint32_t h, l;
        split1(v.x, h, l); { int o = aoff(row, kq*4+0); Hb[o] = h; Lb[o] = l; }
        split1(v.y, h, l); { int o = aoff(row, kq*4+1); Hb[o] = h; Lb[o] = l; }
        split1(v.z, h, l); { int o = aoff(row, kq*4+2); Hb[o] = h; Lb[o] = l; }
        split1(v.w, h, l); { int o = aoff(row, kq*4+3); Hb[o] = h; Lb[o] = l; }
    };
    auto storeBquadT = [&](uint32_t* Hb, uint32_t* Lb, int nrow, int kq, float4 v) {
        uint32_t h, l;
        split1(v.x, h, l); { int o = boff(nrow, kq*4+0); Hb[o] = h; Lb[o] = l; }
        split1(v.y, h, l); { int o = boff(nrow, kq*4+1); Hb[o] = h; Lb[o] = l; }
        split1(v.z, h, l); { int o = boff(nrow, kq*4+2); Hb[o] = h; Lb[o] = l; }
        split1(v.w, h, l); { int o = boff(nrow, kq*4+3); Hb[o] = h; Lb[o] = l; }
    };
    auto storeBquadN = [&](uint32_t* Hb, uint32_t* Lb, int krow, int nq, float4 v) {
        uint32_t h, l;
        split1(v.x, h, l); { int o = boff(nq*4+0, krow); Hb[o] = h; Lb[o] = l; }
        split1(v.y, h, l); { int o = boff(nq*4+1, krow); Hb[o] = h; Lb[o] = l; }
        split1(v.z, h, l); { int o = boff(nq*4+2, krow); Hb[o] = h; Lb[o] = l; }
        split1(v.w, h, l); { int o = boff(nq*4+3, krow); Hb[o] = h; Lb[o] = l; }
    };

    auto storeAll = [&](int buf) {
        uint32_t* AhB = Ah + buf * TILE_WORDS;
        uint32_t* AlB = Al + buf * TILE_WORDS;
        uint32_t* BhB = Bh + buf * TILE_WORDS;
        uint32_t* BlB = Bl + buf * TILE_WORDS;
        storeAquad(AhB, AlB, ar0, ak0, fa0);
        storeAquad(AhB, AlB, ar1, ak1, fa1);
        if (BT) {
            storeBquadT(BhB, BlB, ar0, ak0, fb0);
            storeBquadT(BhB, BlB, ar1, ak1, fb1);
        } else {
            storeBquadN(BhB, BlB, kr0, cq0, fb0);
            storeBquadN(BhB, BlB, kr1, cq1, fb1);
        }
    };

    float acc[4][4][4];   // [mt][nt][frag]
#pragma unroll
    for (int mt = 0; mt < 4; mt++)
#pragma unroll
        for (int nt = 0; nt < 4; nt++)
#pragma unroll
            for (int r = 0; r < 4; r++) acc[mt][nt][r] = 0.f;

    // Prologue
    fetchA(0); fetchB(0);
    storeAll(0);
    __syncthreads();

    int cur = 0;
    for (int k0 = 16; k0 <= K; k0 += 16) {
        const bool more = (k0 < K);
        if (more) { fetchA(k0); fetchB(k0); }   // LDGs overlap compute

        const uint32_t* AhC = Ah + cur * TILE_WORDS;
        const uint32_t* AlC = Al + cur * TILE_WORDS;
        const uint32_t* BhC = Bh + cur * TILE_WORDS;
        const uint32_t* BlC = Bl + cur * TILE_WORDS;

#pragma unroll
        for (int ks = 0; ks < 2; ks++) {
            // B fragments: one LDS.64 (hi) + one (lo) per nt
            uint32_t bh[4][2], bl[4][2];
#pragma unroll
            for (int nt = 0; nt < 4; nt++) {
                const int bbase = ((((wn >> 3) + nt) << 1) + ks) * 64 + lane * 2;
                uint2 vh = *reinterpret_cast<const uint2*>(BhC + bbase);
                uint2 vl = *reinterpret_cast<const uint2*>(BlC + bbase);
                bh[nt][0] = vh.x; bh[nt][1] = vh.y;
                bl[nt][0] = vl.x; bl[nt][1] = vl.y;
            }
            // A fragments: one LDS.128 (hi) + one (lo) per mt
#pragma unroll
            for (int mt = 0; mt < 4; mt++) {
                const int abase = ((((wm >> 4) + mt) << 1) + ks) * 128 + lane * 4;
                uint4 vh = *reinterpret_cast<const uint4*>(AhC + abase);
                uint4 vl = *reinterpret_cast<const uint4*>(AlC + abase);
                uint32_t ah[4] = {vh.x, vh.y, vh.z, vh.w};
                uint32_t al[4] = {vl.x, vl.y, vl.z, vl.w};
#pragma unroll
                for (int nt = 0; nt < 4; nt++) {
                    mma_tf32(acc[mt][nt], ah, bh[nt]);
                    mma_tf32(acc[mt][nt], ah, bl[nt]);
                    mma_tf32(acc[mt][nt], al, bh[nt]);
                }
            }
        }

        if (more) {
            storeAll(cur ^ 1);      // disjoint buffer; prior reads fenced by last sync
            __syncthreads();
            cur ^= 1;
        }
    }

    // ---- epilogue: fragment layout -> global ----
#pragma unroll
    for (int mt = 0; mt < 4; mt++) {
        const int r0 = bm + wm + mt * 16 + g;
#pragma unroll
        for (int nt = 0; nt < 4; nt++) {
            const int c0 = bn + wn + nt * 8 + 2 * tg;
            float2 v0 = make_float2(acc[mt][nt][0], acc[mt][nt][1]);
            float2 v1 = make_float2(acc[mt][nt][2], acc[mt][nt][3]);
            if (EPI == 1) {
                v0.x += E[c0];     v0.y += E[c0 + 1];
                v1.x += E[c0];     v1.y += E[c0 + 1];
            } else if (EPI == 2) {
                const float* mask = E + (size_t)bz * N;
                const float p0 = (1.f - mask[c0])     * -10000.f;
                const float p1 = (1.f - mask[c0 + 1]) * -10000.f;
                v0.x = v0.x * scale + p0;  v0.y = v0.y * scale + p1;
                v1.x = v1.x * scale + p0;  v1.y = v1.y * scale + p1;
            }
            *reinterpret_cast<float2*>(Cb + (size_t)r0 * N + c0)       = v0;
            *reinterpret_cast<float2*>(Cb + (size_t)(r0 + 8) * N + c0) = v1;
        }
    }
}

// ---------------------------------------------------------------------------
// Row softmax over N=2048, one block (256 threads) per row, in place.
// ---------------------------------------------------------------------------
__device__ __forceinline__ float warp_max(float v) {
#pragma unroll
    for (int o = 16; o; o >>= 1) v = fmaxf(v, __shfl_xor_sync(0xFFFFFFFFu, v, o));
    return v;
}
__device__ __forceinline__ float warp_sum(float v) {
#pragma unroll
    for (int o = 16; o; o >>= 1) v += __shfl_xor_sync(0xFFFFFFFFu, v, o);
    return v;
}

__global__ __launch_bounds__(256)
void softmax_kern(float* __restrict__ S)
{
    const size_t row = blockIdx.x;
    float* p = S + row * (size_t)SKV;
    const int tid = threadIdx.x;

    float4 v0 = *reinterpret_cast<const float4*>(p + tid * 4);
    float4 v1 = *reinterpret_cast<const float4*>(p + 1024 + tid * 4);

    float m = fmaxf(fmaxf(fmaxf(v0.x, v0.y), fmaxf(v0.z, v0.w)),
                    fmaxf(fmaxf(v1.x, v1.y), fmaxf(v1.z, v1.w)));

    __shared__ float red[8];
    float wm = warp_max(m);
    if ((tid & 31) == 0) red[tid >> 5] = wm;
    __syncthreads();
    float bm = red[0];
#pragma unroll
    for (int i = 1; i < 8; i++) bm = fmaxf(bm, red[i]);
    __syncthreads();

    v0.x = expf(v0.x - bm); v0.y = expf(v0.y - bm);
    v0.z = expf(v0.z - bm); v0.w = expf(v0.w - bm);
    v1.x = expf(v1.x - bm); v1.y = expf(v1.y - bm);
    v1.z = expf(v1.z - bm); v1.w = expf(v1.w - bm);

    float s = v0.x + v0.y + v0.z + v0.w + v1.x + v1.y + v1.z + v1.w;
    float ws = warp_sum(s);
    if ((tid & 31) == 0) red[tid >> 5] = ws;
    __syncthreads();
    float bs = 0.f;
#pragma unroll
    for (int i = 0; i < 8; i++) bs += red[i];

    const float inv = 1.f / bs;
    v0.x *= inv; v0.y *= inv; v0.z *= inv; v0.w *= inv;
    v1.x *= inv; v1.y *= inv; v1.z *= inv; v1.w *= inv;

    *reinterpret_cast<float4*>(p + tid * 4)        = v0;
    *reinterpret_cast<float4*>(p + 1024 + tid * 4) = v1;
}

// ---------------------------------------------------------------------------
// Launch
// ---------------------------------------------------------------------------
extern "C" void kernel_launch(void* const* d_in, const int* in_sizes, int n_in,
                              void* d_out, int out_size)
{
    const float* Xq   = (const float*)d_in[0];  // [B,Sq,H]
    const float* Xk   = (const float*)d_in[1];  // [B,Skv,H]
    const float* mask = (const float*)d_in[2];  // [B,Skv]
    const float* Wq   = (const float*)d_in[3];  // [H,H]
    const float* bq   = (const float*)d_in[4];
    const float* Wk   = (const float*)d_in[5];
    const float* bk   = (const float*)d_in[6];
    const float* Wv   = (const float*)d_in[7];
    const float* bv   = (const float*)d_in[8];
    float* out = (float*)d_out;                 // [B,Sq,H]

    float *Q, *K, *V, *S;
    cudaGetSymbolAddress((void**)&Q, g_Q);
    cudaGetSymbolAddress((void**)&K, g_K);
    cudaGetSymbolAddress((void**)&V, g_V);
    cudaGetSymbolAddress((void**)&S, g_S);

    // Dynamic smem above 48KB needs an opt-in (host-side attr; capture-safe)
    cudaFuncSetAttribute(gemm_kern<false, 1>,
        cudaFuncAttributeMaxDynamicSharedMemorySize, SMEM_BYTES);
    cudaFuncSetAttribute(gemm_kern<true, 2>,
        cudaFuncAttributeMaxDynamicSharedMemorySize, SMEM_BYTES);
    cudaFuncSetAttribute(gemm_kern<false, 0>,
        cudaFuncAttributeMaxDynamicSharedMemorySize, SMEM_BYTES);

    const float scale = 1.f / 32.f;  // 1/sqrt(1024)

    // 1-3) Projections: [B*S, H] @ [H, H] + bias, NN
    {
        dim3 grid(HID / 128, (BATCH * SQ) / 128, 1);
        gemm_kern<false, 1><<<grid, 256, SMEM_BYTES>>>(Xq, Wq, bq, Q,
            BATCH * SQ, HID, HID, 0, 0, 0, 1.f);
        gemm_kern<false, 1><<<grid, 256, SMEM_BYTES>>>(Xk, Wk, bk, K,
            BATCH * SKV, HID, HID, 0, 0, 0, 1.f);
        gemm_kern<false, 1><<<grid, 256, SMEM_BYTES>>>(Xk, Wv, bv, V,
            BATCH * SKV, HID, HID, 0, 0, 0, 1.f);
    }

    // 4) Scores: S[b] = Q[b] @ K[b]^T * scale + (1-mask)*-1e4  (NT, batched)
    {
        dim3 grid(SKV / 128, SQ / 128, BATCH);
        gemm_kern<true, 2><<<grid, 256, SMEM_BYTES>>>(Q, K, mask, S,
            SQ, SKV, HID,
            (size_t)SQ * HID, (size_t)SKV * HID, (size_t)SQ * SKV, scale);
    }

    // 5) Row softmax in place
    softmax_kern<<<BATCH * SQ, 256>>>(S);

    // 6) Output: out[b] = S[b] @ V[b]  (NN, batched)
    {
        dim3 grid(HID / 128, SQ / 128, BATCH);
        gemm_kern<false, 0><<<grid, 256, SMEM_BYTES>>>(S, V, nullptr, out,
            SQ, HID, SKV,
            (size_t)SQ * SKV, (size_t)SKV * HID, (size_t)SQ * HID, 1.f);
    }
}

// round 8
// speedup vs baseline: 3.2492x; 3.2492x over previous
#include <cuda_runtime.h>
#include <cuda_bf16.h>
#include <stdint.h>
#include <math.h>

// Problem dims (fixed by reference setup_inputs)
#define BATCH 8
#define SQ    2048
#define SKV   2048
#define HID   1024

#define NX ((size_t)BATCH * SQ * HID)     // 16,777,216
#define NW ((size_t)HID * HID)            // 1,048,576
#define NS ((size_t)BATCH * SQ * SKV)     // 33,554,432

// ---------------------------------------------------------------------------
// Scratch (allocation-free rule: __device__ globals)
// ---------------------------------------------------------------------------
__device__ __nv_bfloat16 gXqh[NX], gXql[NX];
__device__ __nv_bfloat16 gXkh[NX], gXkl[NX];
__device__ __nv_bfloat16 gWqth[NW], gWqtl[NW];
__device__ __nv_bfloat16 gWkth[NW], gWktl[NW];
__device__ __nv_bfloat16 gWvth[NW], gWvtl[NW];
__device__ __nv_bfloat16 gQh[NX], gQl[NX];
__device__ __nv_bfloat16 gKh[NX], gKl[NX];
__device__ __nv_bfloat16 gVth[NX], gVtl[NX];   // [HID][BATCH*SKV]  (V transposed)
__device__ float         gS[NS];
__device__ __nv_bfloat16 gSh[NS], gSl[NS];

// ---------------------------------------------------------------------------
// helpers
// ---------------------------------------------------------------------------
__device__ __forceinline__ void split2(float v, __nv_bfloat16& h, __nv_bfloat16& l) {
    h = __float2bfloat16(v);
    l = __float2bfloat16(v - __bfloat162float(h));
}

__device__ __forceinline__ void split4(__nv_bfloat16* H, __nv_bfloat16* L,
                                       size_t idx, float4 v) {
    __nv_bfloat16 h0, h1, h2, h3, l0, l1, l2, l3;
    split2(v.x, h0, l0); split2(v.y, h1, l1);
    split2(v.z, h2, l2); split2(v.w, h3, l3);
    __nv_bfloat162 a, b;
    a.x = h0; a.y = h1; b.x = h2; b.y = h3;
    *reinterpret_cast<__nv_bfloat162*>(H + idx)     = a;
    *reinterpret_cast<__nv_bfloat162*>(H + idx + 2) = b;
    a.x = l0; a.y = l1; b.x = l2; b.y = l3;
    *reinterpret_cast<__nv_bfloat162*>(L + idx)     = a;
    *reinterpret_cast<__nv_bfloat162*>(L + idx + 2) = b;
}

// mma.sync m16n8k16 bf16 -> fp32 accumulate
__device__ __forceinline__ void mma_bf16(float* d, const uint32_t* a, const uint32_t* b) {
    asm volatile(
        "mma.sync.aligned.m16n8k16.row.col.f32.bf16.bf16.f32 "
        "{%0,%1,%2,%3}, {%4,%5,%6,%7}, {%8,%9}, {%0,%1,%2,%3};"
        : "+f"(d[0]), "+f"(d[1]), "+f"(d[2]), "+f"(d[3])
        : "r"(a[0]), "r"(a[1]), "r"(a[2]), "r"(a[3]),
          "r"(b[0]), "r"(b[1]));
}

// Fragment-packed smem word offsets (uint32 = bf16 pair along k), per BK=16 stage.
// A element pair (m 0..127, p 0..7):  lane=(m&7)*4+(p&3), reg=((p>>2)<<1)|((m>>3)&1)
//   -> one LDS.128 per A fragment (m16 x k16 tile).
__device__ __forceinline__ int aoffp(int m, int p) {
    return ((m >> 4) << 7) + ((m & 7) << 4) + ((p & 3) << 2)
         + (((p >> 2) << 1) | ((m >> 3) & 1));
}
// B element pair (n 0..127, p 0..7):  lane=(n&7)*4+(p&3), reg=p>>2
//   -> one LDS.64 per B fragment (n8 x k16 tile).
__device__ __forceinline__ int boffp(int n, int p) {
    return ((n >> 3) << 6) + ((n & 7) << 3) + ((p & 3) << 1) + (p >> 2);
}

// ---------------------------------------------------------------------------
// bf16 3-term tensor-core GEMM: C[M,N] = A * B^T (+epilogue), hi/lo operands.
//   A: [M rows][K] bf16 hi/lo (K-major). B: [N rows][K] bf16 hi/lo (K-major).
//   Per-batch: ptr + bz*bstride, rows stride a_rs/b_rs.
// EPI: 0 plain fp32 | 1 +bias[n] -> hi/lo bf16 out
//      2 scores: v*scale + (1-mask[bz*e_s+n])*(-1e4), fp32 out
//      3 +bias[m] -> hi/lo bf16 out  (used for V^T)
// Block 128x128, BK=16, 256 threads = 8 warps (2x4), warp tile 64x32.
// acc = ah*bh + ah*bl + al*bh, term-major mma order (16 indep accumulators
// between same-acc reuses). Double-buffered fragment-packed smem, 32 KB.
// ---------------------------------------------------------------------------
template<int EPI>
__global__ __launch_bounds__(256)
void gemm_bf(const __nv_bfloat16* __restrict__ Agh, const __nv_bfloat16* __restrict__ Agl,
             size_t a_bs, int a_rs,
             const __nv_bfloat16* __restrict__ Bgh, const __nv_bfloat16* __restrict__ Bgl,
             size_t b_bs, int b_rs,
             float* __restrict__ Cf, __nv_bfloat16* __restrict__ Ch, __nv_bfloat16* __restrict__ Cl,
             size_t c_bs, int c_ld,
             const float* __restrict__ E, int e_s, float scale, int K)
{
    __shared__ uint32_t sm[2][4][1024];   // [stage][Ah,Al,Bh,Bl][word]  32 KB

    const int tid  = threadIdx.x;
    const int wid  = tid >> 5;
    const int lane = tid & 31;
    const int g  = lane >> 2;
    const int tg = lane & 3;
    const int bz = blockIdx.z;
    const int bm = blockIdx.y * 128;
    const int bn = blockIdx.x * 128;
    const int wm = (wid >> 2) * 64;
    const int wn = (wid & 3) * 32;

    const __nv_bfloat16* Ah = Agh + (size_t)bz * a_bs;
    const __nv_bfloat16* Al = Agl + (size_t)bz * a_bs;
    const __nv_bfloat16* Bh = Bgh + (size_t)bz * b_bs;
    const __nv_bfloat16* Bl = Bgl + (size_t)bz * b_bs;

    // staging: thread -> (row r, k-half). uint4 = 8 bf16 = pairs p0..p0+3.
    const int r    = tid >> 1;
    const int half = tid & 1;
    const int p0   = half * 4;
    int ao[4], bo[4];
#pragma unroll
    for (int i = 0; i < 4; i++) { ao[i] = aoffp(r, p0 + i); bo[i] = boffp(r, p0 + i); }

    const size_t gaBase = (size_t)(bm + r) * a_rs + half * 8;
    const size_t gbBase = (size_t)(bn + r) * b_rs + half * 8;

    float acc[4][4][4];
#pragma unroll
    for (int mt = 0; mt < 4; mt++)
#pragma unroll
        for (int nt = 0; nt < 4; nt++)
#pragma unroll
            for (int q = 0; q < 4; q++) acc[mt][nt][q] = 0.f;

    // prologue: stage chunk 0 into buffer 0
    {
        uint4 va = *reinterpret_cast<const uint4*>(Ah + gaBase);
        uint4 wa = *reinterpret_cast<const uint4*>(Al + gaBase);
        uint4 vb = *reinterpret_cast<const uint4*>(Bh + gbBase);
        uint4 wb = *reinterpret_cast<const uint4*>(Bl + gbBase);
        sm[0][0][ao[0]] = va.x; sm[0][0][ao[1]] = va.y; sm[0][0][ao[2]] = va.z; sm[0][0][ao[3]] = va.w;
        sm[0][1][ao[0]] = wa.x; sm[0][1][ao[1]] = wa.y; sm[0][1][ao[2]] = wa.z; sm[0][1][ao[3]] = wa.w;
        sm[0][2][bo[0]] = vb.x; sm[0][2][bo[1]] = vb.y; sm[0][2][bo[2]] = vb.z; sm[0][2][bo[3]] = vb.w;
        sm[0][3][bo[0]] = wb.x; sm[0][3][bo[1]] = wb.y; sm[0][3][bo[2]] = wb.z; sm[0][3][bo[3]] = wb.w;
    }
    __syncthreads();

    const int NCH = K >> 4;
    for (int c = 0; c < NCH; c++) {
        const int st = c & 1;
        const bool more = (c + 1) < NCH;

        // prefetch next chunk into registers (LDGs overlap compute)
        uint4 va, wa, vb, wb;
        if (more) {
            const int k0 = (c + 1) << 4;
            va = *reinterpret_cast<const uint4*>(Ah + gaBase + k0);
            wa = *reinterpret_cast<const uint4*>(Al + gaBase + k0);
            vb = *reinterpret_cast<const uint4*>(Bh + gbBase + k0);
            wb = *reinterpret_cast<const uint4*>(Bl + gbBase + k0);
        }

        // load B fragments (hi + lo): LDS.64 each
        uint32_t bh[4][2], bl[4][2];
#pragma unroll
        for (int nt = 0; nt < 4; nt++) {
            const int bbase = (((wn >> 3) + nt) << 6) + lane * 2;
            uint2 h2 = *reinterpret_cast<const uint2*>(&sm[st][2][bbase]);
            uint2 l2 = *reinterpret_cast<const uint2*>(&sm[st][3][bbase]);
            bh[nt][0] = h2.x; bh[nt][1] = h2.y;
            bl[nt][0] = l2.x; bl[nt][1] = l2.y;
        }
        // load A-hi fragments: LDS.128 each
        uint32_t af[4][4];
#pragma unroll
        for (int mt = 0; mt < 4; mt++) {
            const int abase = (((wm >> 4) + mt) << 7) + lane * 4;
            uint4 h4 = *reinterpret_cast<const uint4*>(&sm[st][0][abase]);
            af[mt][0] = h4.x; af[mt][1] = h4.y; af[mt][2] = h4.z; af[mt][3] = h4.w;
        }

        // term 0: ah * bh   (term-major: 16 independent accs between reuses)
#pragma unroll
        for (int mt = 0; mt < 4; mt++)
#pragma unroll
            for (int nt = 0; nt < 4; nt++)
                mma_bf16(acc[mt][nt], af[mt], bh[nt]);
        // term 1: ah * bl
#pragma unroll
        for (int mt = 0; mt < 4; mt++)
#pragma unroll
            for (int nt = 0; nt < 4; nt++)
                mma_bf16(acc[mt][nt], af[mt], bl[nt]);
        // term 2: al * bh (reload A as lo)
#pragma unroll
        for (int mt = 0; mt < 4; mt++) {
            const int abase = (((wm >> 4) + mt) << 7) + lane * 4;
            uint4 l4 = *reinterpret_cast<const uint4*>(&sm[st][1][abase]);
            af[mt][0] = l4.x; af[mt][1] = l4.y; af[mt][2] = l4.z; af[mt][3] = l4.w;
        }
#pragma unroll
        for (int mt = 0; mt < 4; mt++)
#pragma unroll
            for (int nt = 0; nt < 4; nt++)
                mma_bf16(acc[mt][nt], af[mt], bh[nt]);

        if (more) {
            const int nx = st ^ 1;
            sm[nx][0][ao[0]] = va.x; sm[nx][0][ao[1]] = va.y; sm[nx][0][ao[2]] = va.z; sm[nx][0][ao[3]] = va.w;
            sm[nx][1][ao[0]] = wa.x; sm[nx][1][ao[1]] = wa.y; sm[nx][1][ao[2]] = wa.z; sm[nx][1][ao[3]] = wa.w;
            sm[nx][2][bo[0]] = vb.x; sm[nx][2][bo[1]] = vb.y; sm[nx][2][bo[2]] = vb.z; sm[nx][2][bo[3]] = vb.w;
            sm[nx][3][bo[0]] = wb.x; sm[nx][3][bo[1]] = wb.y; sm[nx][3][bo[2]] = wb.z; sm[nx][3][bo[3]] = wb.w;
            __syncthreads();
        }
    }

    // ---- epilogue: c0,c1 = (row wm+mt*16+g, cols 2tg,2tg+1); c2,c3 row +8 ----
#pragma unroll
    for (int mt = 0; mt < 4; mt++) {
        const int r0 = bm + wm + mt * 16 + g;
#pragma unroll
        for (int nt = 0; nt < 4; nt++) {
            const int c0 = bn + wn + nt * 8 + 2 * tg;
            float2 v0 = make_float2(acc[mt][nt][0], acc[mt][nt][1]);   // row r0
            float2 v1 = make_float2(acc[mt][nt][2], acc[mt][nt][3]);   // row r0+8
            if (EPI == 0 || EPI == 2) {
                if (EPI == 2) {
                    const float* mk = E + (size_t)bz * e_s;
                    const float q0 = (1.f - mk[c0])     * -10000.f;
                    const float q1 = (1.f - mk[c0 + 1]) * -10000.f;
                    v0.x = v0.x * scale + q0;  v0.y = v0.y * scale + q1;
                    v1.x = v1.x * scale + q0;  v1.y = v1.y * scale + q1;
                }
                float* Cb = Cf + (size_t)bz * c_bs;
                *reinterpret_cast<float2*>(Cb + (size_t)r0 * c_ld + c0)       = v0;
                *reinterpret_cast<float2*>(Cb + (size_t)(r0 + 8) * c_ld + c0) = v1;
            } else {
                if (EPI == 1) {
                    v0.x += E[c0]; v0.y += E[c0 + 1];
                    v1.x += E[c0]; v1.y += E[c0 + 1];
                } else {  // EPI == 3: bias by row
                    v0.x += E[r0];     v0.y += E[r0];
                    v1.x += E[r0 + 8]; v1.y += E[r0 + 8];
                }
                __nv_bfloat16 h0, l0, h1, l1;
                __nv_bfloat162 hp, lp;
                split2(v0.x, h0, l0); split2(v0.y, h1, l1);
                hp.x = h0; hp.y = h1; lp.x = l0; lp.y = l1;
                *reinterpret_cast<__nv_bfloat162*>(Ch + (size_t)r0 * c_ld + c0) = hp;
                *reinterpret_cast<__nv_bfloat162*>(Cl + (size_t)r0 * c_ld + c0) = lp;
                split2(v1.x, h0, l0); split2(v1.y, h1, l1);
                hp.x = h0; hp.y = h1; lp.x = l0; lp.y = l1;
                *reinterpret_cast<__nv_bfloat162*>(Ch + (size_t)(r0 + 8) * c_ld + c0) = hp;
                *reinterpret_cast<__nv_bfloat162*>(Cl + (size_t)(r0 + 8) * c_ld + c0) = lp;
            }
        }
    }
}

// ---------------------------------------------------------------------------
// Pre-pass: fp32 -> bf16 hi/lo split (one float4 per thread)
// ---------------------------------------------------------------------------
__global__ __launch_bounds__(256)
void split_kern(const float* __restrict__ X, __nv_bfloat16* __restrict__ H,
                __nv_bfloat16* __restrict__ L, int n4)
{
    int i = blockIdx.x * blockDim.x + threadIdx.x;
    if (i >= n4) return;
    float4 v = reinterpret_cast<const float4*>(X)[i];
    split4(H, L, (size_t)i * 4, v);
}

// ---------------------------------------------------------------------------
// Pre-pass: weight transpose + split. W[in=k][out=n] fp32 -> Wt[n][k] hi/lo.
// ---------------------------------------------------------------------------
__global__ __launch_bounds__(256)
void tsplit_kern(const float* __restrict__ W, __nv_bfloat16* __restrict__ TH,
                 __nv_bfloat16* __restrict__ TL)
{
    __shared__ float t[32][33];
    const int bx = blockIdx.x * 32;   // n
    const int by = blockIdx.y * 32;   // k
    const int x = threadIdx.x & 31;
    const int y = threadIdx.x >> 5;
#pragma unroll
    for (int i = 0; i < 4; i++)
        t[y + 8 * i][x] = W[(size_t)(by + y + 8 * i) * HID + bx + x];
    __syncthreads();
#pragma unroll
    for (int i = 0; i < 4; i++) {
        const int n = bx + y + 8 * i, k = by + x;
        __nv_bfloat16 h, l;
        split2(t[x][y + 8 * i], h, l);
        TH[(size_t)n * HID + k] = h;
        TL[(size_t)n * HID + k] = l;
    }
}

// ---------------------------------------------------------------------------
// Row softmax over N=2048; reads fp32 scores, writes bf16 hi/lo probs.
// ---------------------------------------------------------------------------
__device__ __forceinline__ float warp_max(float v) {
#pragma unroll
    for (int o = 16; o; o >>= 1) v = fmaxf(v, __shfl_xor_sync(0xFFFFFFFFu, v, o));
    return v;
}
__device__ __forceinline__ float warp_sum(float v) {
#pragma unroll
    for (int o = 16; o; o >>= 1) v += __shfl_xor_sync(0xFFFFFFFFu, v, o);
    return v;
}

__global__ __launch_bounds__(256)
void softmax_kern(const float* __restrict__ S, __nv_bfloat16* __restrict__ Ph,
                  __nv_bfloat16* __restrict__ Pl)
{
    const size_t row = blockIdx.x;
    const float* p = S + row * (size_t)SKV;
    const int tid = threadIdx.x;

    float4 v0 = *reinterpret_cast<const float4*>(p + tid * 4);
    float4 v1 = *reinterpret_cast<const float4*>(p + 1024 + tid * 4);

    float m = fmaxf(fmaxf(fmaxf(v0.x, v0.y), fmaxf(v0.z, v0.w)),
                    fmaxf(fmaxf(v1.x, v1.y), fmaxf(v1.z, v1.w)));

    __shared__ float red[8];
    float wm = warp_max(m);
    if ((tid & 31) == 0) red[tid >> 5] = wm;
    __syncthreads();
    float bm = red[0];
#pragma unroll
    for (int i = 1; i < 8; i++) bm = fmaxf(bm, red[i]);
    __syncthreads();

    v0.x = expf(v0.x - bm); v0.y = expf(v0.y - bm);
    v0.z = expf(v0.z - bm); v0.w = expf(v0.w - bm);
    v1.x = expf(v1.x - bm); v1.y = expf(v1.y - bm);
    v1.z = expf(v1.z - bm); v1.w = expf(v1.w - bm);

    float s = v0.x + v0.y + v0.z + v0.w + v1.x + v1.y + v1.z + v1.w;
    float ws = warp_sum(s);
    if ((tid & 31) == 0) red[tid >> 5] = ws;
    __syncthreads();
    float bs = 0.f;
#pragma unroll
    for (int i = 0; i < 8; i++) bs += red[i];

    const float inv = 1.f / bs;
    v0.x *= inv; v0.y *= inv; v0.z *= inv; v0.w *= inv;
    v1.x *= inv; v1.y *= inv; v1.z *= inv; v1.w *= inv;

    split4(Ph, Pl, row * (size_t)SKV + tid * 4, v0);
    split4(Ph, Pl, row * (size_t)SKV + 1024 + tid * 4, v1);
}

// ---------------------------------------------------------------------------
// Launch
// ---------------------------------------------------------------------------
extern "C" void kernel_launch(void* const* d_in, const int* in_sizes, int n_in,
                              void* d_out, int out_size)
{
    const float* Xq   = (const float*)d_in[0];
    const float* Xk   = (const float*)d_in[1];
    const float* mask = (const float*)d_in[2];
    const float* Wq   = (const float*)d_in[3];
    const float* bq   = (const float*)d_in[4];
    const float* Wk   = (const float*)d_in[5];
    const float* bk   = (const float*)d_in[6];
    const float* Wv   = (const float*)d_in[7];
    const float* bv   = (const float*)d_in[8];
    float* out = (float*)d_out;

    __nv_bfloat16 *Xqh, *Xql, *Xkh, *Xkl, *Wqth, *Wqtl, *Wkth, *Wktl, *Wvth, *Wvtl;
    __nv_bfloat16 *Qh, *Ql, *Kh, *Kl, *Vth, *Vtl, *Sh, *Sl;
    float* S;
    cudaGetSymbolAddress((void**)&Xqh, gXqh);   cudaGetSymbolAddress((void**)&Xql, gXql);
    cudaGetSymbolAddress((void**)&Xkh, gXkh);   cudaGetSymbolAddress((void**)&Xkl, gXkl);
    cudaGetSymbolAddress((void**)&Wqth, gWqth); cudaGetSymbolAddress((void**)&Wqtl, gWqtl);
    cudaGetSymbolAddress((void**)&Wkth, gWkth); cudaGetSymbolAddress((void**)&Wktl, gWktl);
    cudaGetSymbolAddress((void**)&Wvth, gWvth); cudaGetSymbolAddress((void**)&Wvtl, gWvtl);
    cudaGetSymbolAddress((void**)&Qh, gQh);     cudaGetSymbolAddress((void**)&Ql, gQl);
    cudaGetSymbolAddress((void**)&Kh, gKh);     cudaGetSymbolAddress((void**)&Kl, gKl);
    cudaGetSymbolAddress((void**)&Vth, gVth);   cudaGetSymbolAddress((void**)&Vtl, gVtl);
    cudaGetSymbolAddress((void**)&S, gS);
    cudaGetSymbolAddress((void**)&Sh, gSh);     cudaGetSymbolAddress((void**)&Sl, gSl);

    const float scale = 1.f / 32.f;   // 1/sqrt(1024)
    const int n4 = (int)(NX / 4);

    // Pre-pass: split inputs, transpose+split weights
    split_kern<<<(n4 + 255) / 256, 256>>>(Xq, Xqh, Xql, n4);
    split_kern<<<(n4 + 255) / 256, 256>>>(Xk, Xkh, Xkl, n4);
    tsplit_kern<<<dim3(32, 32), 256>>>(Wq, Wqth, Wqtl);
    tsplit_kern<<<dim3(32, 32), 256>>>(Wk, Wkth, Wktl);
    tsplit_kern<<<dim3(32, 32), 256>>>(Wv, Wvth, Wvtl);

    // Q = Xq @ Wq + bq  -> hi/lo, [B*Sq, H]
    gemm_bf<1><<<dim3(HID / 128, (BATCH * SQ) / 128, 1), 256>>>(
        Xqh, Xql, 0, HID, Wqth, Wqtl, 0, HID,
        nullptr, Qh, Ql, 0, HID, bq, 0, 1.f, HID);
    // K = Xk @ Wk + bk
    gemm_bf<1><<<dim3(HID / 128, (BATCH * SQ) / 128, 1), 256>>>(
        Xkh, Xkl, 0, HID, Wkth, Wktl, 0, HID,
        nullptr, Kh, Kl, 0, HID, bk, 0, 1.f, HID);
    // Vt = (Xk @ Wv + bv)^T : A = Wvt [H rows, K=H], B = Xk [B*Skv rows, K=H]
    gemm_bf<3><<<dim3((BATCH * SKV) / 128, HID / 128, 1), 256>>>(
        Wvth, Wvtl, 0, HID, Xkh, Xkl, 0, HID,
        nullptr, Vth, Vtl, 0, BATCH * SKV, bv, 0, 1.f, HID);
    // S = Q @ K^T * scale + mask  (fp32, batched)
    gemm_bf<2><<<dim3(SKV / 128, SQ / 128, BATCH), 256>>>(
        Qh, Ql, (size_t)SQ * HID, HID, Kh, Kl, (size_t)SKV * HID, HID,
        S, nullptr, nullptr, (size_t)SQ * SKV, SKV, mask, SKV, scale, HID);
    // softmax -> hi/lo probs
    softmax_kern<<<BATCH * SQ, 256>>>(S, Sh, Sl);
    // out = P @ V : A = P [Sq rows, K=Skv], B = Vt [H rows, K=Skv per batch]
    gemm_bf<0><<<dim3(HID / 128, SQ / 128, BATCH), 256>>>(
        Sh, Sl, (size_t)SQ * SKV, SKV, Vth, Vtl, (size_t)SKV, BATCH * SKV,
        out, nullptr, nullptr, (size_t)SQ * HID, HID, nullptr, 0, 1.f, SKV);
}

// round 9
// speedup vs baseline: 3.4263x; 1.0545x over previous
#include <cuda_runtime.h>
#include <cuda_bf16.h>
#include <stdint.h>
#include <math.h>

// Problem dims (fixed by reference setup_inputs)
#define BATCH 8
#define SQ    2048
#define SKV   2048
#define HID   1024

#define NX ((size_t)BATCH * SQ * HID)     // 16,777,216
#define NW ((size_t)HID * HID)            // 1,048,576
#define NS ((size_t)BATCH * SQ * SKV)     // 33,554,432

// ---------------------------------------------------------------------------
// Scratch (allocation-free rule: __device__ globals)
// ---------------------------------------------------------------------------
__device__ __nv_bfloat16 gXqh[NX], gXql[NX];
__device__ __nv_bfloat16 gXkh[NX], gXkl[NX];
__device__ __nv_bfloat16 gWqth[NW], gWqtl[NW];
__device__ __nv_bfloat16 gWkth[NW], gWktl[NW];
__device__ __nv_bfloat16 gWvth[NW], gWvtl[NW];
__device__ __nv_bfloat16 gQh[NX], gQl[NX];
__device__ __nv_bfloat16 gKh[NX], gKl[NX];
__device__ __nv_bfloat16 gVth[NX], gVtl[NX];   // [HID][BATCH*SKV]  (V transposed)
__device__ float         gS[NS];
__device__ __nv_bfloat16 gSh[NS], gSl[NS];

// ---------------------------------------------------------------------------
// helpers
// ---------------------------------------------------------------------------
__device__ __forceinline__ void split2(float v, __nv_bfloat16& h, __nv_bfloat16& l) {
    h = __float2bfloat16(v);
    l = __float2bfloat16(v - __bfloat162float(h));
}

__device__ __forceinline__ void split4(__nv_bfloat16* H, __nv_bfloat16* L,
                                       size_t idx, float4 v) {
    __nv_bfloat16 h0, h1, h2, h3, l0, l1, l2, l3;
    split2(v.x, h0, l0); split2(v.y, h1, l1);
    split2(v.z, h2, l2); split2(v.w, h3, l3);
    __nv_bfloat162 a, b;
    a.x = h0; a.y = h1; b.x = h2; b.y = h3;
    *reinterpret_cast<__nv_bfloat162*>(H + idx)     = a;
    *reinterpret_cast<__nv_bfloat162*>(H + idx + 2) = b;
    a.x = l0; a.y = l1; b.x = l2; b.y = l3;
    *reinterpret_cast<__nv_bfloat162*>(L + idx)     = a;
    *reinterpret_cast<__nv_bfloat162*>(L + idx + 2) = b;
}

// mma.sync m16n8k16 bf16 -> fp32 accumulate
__device__ __forceinline__ void mma_bf16(float* d, const uint32_t* a, const uint32_t* b) {
    asm volatile(
        "mma.sync.aligned.m16n8k16.row.col.f32.bf16.bf16.f32 "
        "{%0,%1,%2,%3}, {%4,%5,%6,%7}, {%8,%9}, {%0,%1,%2,%3};"
        : "+f"(d[0]), "+f"(d[1]), "+f"(d[2]), "+f"(d[3])
        : "r"(a[0]), "r"(a[1]), "r"(a[2]), "r"(a[3]),
          "r"(b[0]), "r"(b[1]));
}

// ---------------------------------------------------------------------------
// bf16 3-term tensor-core GEMM: C[M,N] = A * B^T (+epilogue), hi/lo operands.
//   A: [M rows][K] bf16 hi/lo (K-major). B: [N rows][K] bf16 hi/lo (K-major).
// EPI: 0 plain fp32 | 1 +bias[n] -> hi/lo bf16 out
//      2 scores: v*scale + (1-mask)*(-1e4), fp32 out | 3 +bias[m] -> hi/lo out
// Block 128x128, BK=16, 256 threads = 8 warps (2x4), warp tile 64x32.
// acc = ah*bh + ah*bl + al*bh, term-major mma order.
//
// Fragment-packed smem (compute identical to prior round):
//  A word = (m>>4)*128 + (m&7)*16 + (p&3)*4 + ((p>>2)<<1 | (m>>3)&1)
//           -> one LDS.128 per 16x16 A fragment, conflict-free.
//  B word = (n>>3)*64 + (n&7)*8 + (p&3)*2 + (p>>2)
//           -> one LDS.64 per 8x16 B fragment, conflict-free.
// Staging (NEW): thread-to-data mapping chosen so each thread's 4 words per
// array are CONTIGUOUS -> single STS.128 per array, conflict-free phases.
//  A: thread (blk=t>>5, mm=(t&31)>>2, pp=t&3) holds (m=blk*16+mm(+8), p=pp(+4))
//     via 4x LDG.32. B: thread (nb=t>>4, nn=(t&15)>>1, j=t&1) holds
//     (n=nb*8+nn, p in {2j,2j+1,2j+4,2j+5}) via 2x LDG.64.
// Pipeline: prefetch distance 2; store R(c+1) at top of chunk c; LDG(c+2);
// compute; sync. LDG has a full chunk (~1.4K cyc) to land.
// ---------------------------------------------------------------------------
template<int EPI>
__global__ __launch_bounds__(256)
void gemm_bf(const __nv_bfloat16* __restrict__ Agh, const __nv_bfloat16* __restrict__ Agl,
             size_t a_bs, int a_rs,
             const __nv_bfloat16* __restrict__ Bgh, const __nv_bfloat16* __restrict__ Bgl,
             size_t b_bs, int b_rs,
             float* __restrict__ Cf, __nv_bfloat16* __restrict__ Ch, __nv_bfloat16* __restrict__ Cl,
             size_t c_bs, int c_ld,
             const float* __restrict__ E, int e_s, float scale, int K)
{
    __shared__ uint32_t sm[2][4][1024];   // [stage][Ah,Al,Bh,Bl][word]  32 KB

    const int tid  = threadIdx.x;
    const int wid  = tid >> 5;
    const int lane = tid & 31;
    const int g  = lane >> 2;
    const int tg = lane & 3;
    const int bz = blockIdx.z;
    const int bm = blockIdx.y * 128;
    const int bn = blockIdx.x * 128;
    const int wm = (wid >> 2) * 64;
    const int wn = (wid & 3) * 32;

    const __nv_bfloat16* Ah = Agh + (size_t)bz * a_bs;
    const __nv_bfloat16* Al = Agl + (size_t)bz * a_bs;
    const __nv_bfloat16* Bh = Bgh + (size_t)bz * b_bs;
    const __nv_bfloat16* Bl = Bgl + (size_t)bz * b_bs;

    // ---- staging indices (A side) ----
    const int ablk = tid >> 5;              // m block (0..7)
    const int amm  = (tid & 31) >> 2;       // m&7
    const int app  = tid & 3;               // p&3
    const int aword = ablk * 128 + (tid & 31) * 4;
    const size_t a00 = (size_t)(bm + ablk * 16 + amm) * a_rs + 2 * app; // (m, pp)
    const size_t a10 = a00 + (size_t)8 * a_rs;                         // (m+8, pp)
    // ---- staging indices (B side) ----
    const int bnb = tid >> 4;               // n>>3 (0..15)
    const int bnn = (tid & 15) >> 1;        // n&7
    const int bj  = tid & 1;                // p&3 half (p&3 in {2j,2j+1})
    const int bword = bnb * 64 + bnn * 8 + bj * 4;
    const size_t b00 = (size_t)(bn + bnb * 8 + bnn) * b_rs + 4 * bj;   // elems 4j..4j+3

    // prefetch registers (one chunk of all 4 arrays)
    uint32_t Rah0, Rah1, Rah2, Rah3, Ral0, Ral1, Ral2, Ral3;
    uint2 Rbh0, Rbh1, Rbl0, Rbl1;

    auto loadR = [&](int c) {
        const size_t k = (size_t)c << 4;
        Rah0 = *reinterpret_cast<const uint32_t*>(Ah + a00 + k);
        Rah1 = *reinterpret_cast<const uint32_t*>(Ah + a10 + k);
        Rah2 = *reinterpret_cast<const uint32_t*>(Ah + a00 + k + 8);
        Rah3 = *reinterpret_cast<const uint32_t*>(Ah + a10 + k + 8);
        Ral0 = *reinterpret_cast<const uint32_t*>(Al + a00 + k);
        Ral1 = *reinterpret_cast<const uint32_t*>(Al + a10 + k);
        Ral2 = *reinterpret_cast<const uint32_t*>(Al + a00 + k + 8);
        Ral3 = *reinterpret_cast<const uint32_t*>(Al + a10 + k + 8);
        Rbh0 = *reinterpret_cast<const uint2*>(Bh + b00 + k);
        Rbh1 = *reinterpret_cast<const uint2*>(Bh + b00 + k + 8);
        Rbl0 = *reinterpret_cast<const uint2*>(Bl + b00 + k);
        Rbl1 = *reinterpret_cast<const uint2*>(Bl + b00 + k + 8);
    };
    auto storeR = [&](int buf) {
        *reinterpret_cast<uint4*>(&sm[buf][0][aword]) = make_uint4(Rah0, Rah1, Rah2, Rah3);
        *reinterpret_cast<uint4*>(&sm[buf][1][aword]) = make_uint4(Ral0, Ral1, Ral2, Ral3);
        *reinterpret_cast<uint4*>(&sm[buf][2][bword]) = make_uint4(Rbh0.x, Rbh1.x, Rbh0.y, Rbh1.y);
        *reinterpret_cast<uint4*>(&sm[buf][3][bword]) = make_uint4(Rbl0.x, Rbl1.x, Rbl0.y, Rbl1.y);
    };

    float acc[4][4][4];
#pragma unroll
    for (int mt = 0; mt < 4; mt++)
#pragma unroll
        for (int nt = 0; nt < 4; nt++)
#pragma unroll
            for (int q = 0; q < 4; q++) acc[mt][nt][q] = 0.f;

    const int NCH = K >> 4;

    // prologue
    loadR(0); storeR(0);
    loadR(1);
    __syncthreads();

    for (int c = 0; c < NCH; c++) {
        const int st = c & 1;
        if (c + 1 < NCH) storeR(st ^ 1);   // R holds chunk c+1; buf free since sync(c-1)
        if (c + 2 < NCH) loadR(c + 2);     // full chunk of time to land

        // B-hi fragments: LDS.64 each
        uint32_t bh[4][2];
#pragma unroll
        for (int nt = 0; nt < 4; nt++) {
            const int bbase = (((wn >> 3) + nt) << 6) + lane * 2;
            uint2 h2 = *reinterpret_cast<const uint2*>(&sm[st][2][bbase]);
            bh[nt][0] = h2.x; bh[nt][1] = h2.y;
        }
        // A-hi fragments: LDS.128 each
        uint32_t af[4][4];
#pragma unroll
        for (int mt = 0; mt < 4; mt++) {
            const int abase = (((wm >> 4) + mt) << 7) + lane * 4;
            uint4 h4 = *reinterpret_cast<const uint4*>(&sm[st][0][abase]);
            af[mt][0] = h4.x; af[mt][1] = h4.y; af[mt][2] = h4.z; af[mt][3] = h4.w;
        }

        // term 0: ah * bh (term-major: 16 indep accumulators between reuses)
#pragma unroll
        for (int mt = 0; mt < 4; mt++)
#pragma unroll
            for (int nt = 0; nt < 4; nt++)
                mma_bf16(acc[mt][nt], af[mt], bh[nt]);

        // term 1: ah * bl
        uint32_t bl[4][2];
#pragma unroll
        for (int nt = 0; nt < 4; nt++) {
            const int bbase = (((wn >> 3) + nt) << 6) + lane * 2;
            uint2 l2 = *reinterpret_cast<const uint2*>(&sm[st][3][bbase]);
            bl[nt][0] = l2.x; bl[nt][1] = l2.y;
        }
#pragma unroll
        for (int mt = 0; mt < 4; mt++)
#pragma unroll
            for (int nt = 0; nt < 4; nt++)
                mma_bf16(acc[mt][nt], af[mt], bl[nt]);

        // term 2: al * bh (reload A as lo)
#pragma unroll
        for (int mt = 0; mt < 4; mt++) {
            const int abase = (((wm >> 4) + mt) << 7) + lane * 4;
            uint4 l4 = *reinterpret_cast<const uint4*>(&sm[st][1][abase]);
            af[mt][0] = l4.x; af[mt][1] = l4.y; af[mt][2] = l4.z; af[mt][3] = l4.w;
        }
#pragma unroll
        for (int mt = 0; mt < 4; mt++)
#pragma unroll
            for (int nt = 0; nt < 4; nt++)
                mma_bf16(acc[mt][nt], af[mt], bh[nt]);

        if (c + 1 < NCH) __syncthreads();
    }

    // ---- epilogue ----
#pragma unroll
    for (int mt = 0; mt < 4; mt++) {
        const int r0 = bm + wm + mt * 16 + g;
#pragma unroll
        for (int nt = 0; nt < 4; nt++) {
            const int c0 = bn + wn + nt * 8 + 2 * tg;
            float2 v0 = make_float2(acc[mt][nt][0], acc[mt][nt][1]);   // row r0
            float2 v1 = make_float2(acc[mt][nt][2], acc[mt][nt][3]);   // row r0+8
            if (EPI == 0 || EPI == 2) {
                if (EPI == 2) {
                    const float* mk = E + (size_t)bz * e_s;
                    const float q0 = (1.f - mk[c0])     * -10000.f;
                    const float q1 = (1.f - mk[c0 + 1]) * -10000.f;
                    v0.x = v0.x * scale + q0;  v0.y = v0.y * scale + q1;
                    v1.x = v1.x * scale + q0;  v1.y = v1.y * scale + q1;
                }
                float* Cb = Cf + (size_t)bz * c_bs;
                *reinterpret_cast<float2*>(Cb + (size_t)r0 * c_ld + c0)       = v0;
                *reinterpret_cast<float2*>(Cb + (size_t)(r0 + 8) * c_ld + c0) = v1;
            } else {
                if (EPI == 1) {
                    v0.x += E[c0]; v0.y += E[c0 + 1];
                    v1.x += E[c0]; v1.y += E[c0 + 1];
                } else {  // EPI == 3: bias by row
                    v0.x += E[r0];     v0.y += E[r0];
                    v1.x += E[r0 + 8]; v1.y += E[r0 + 8];
                }
                __nv_bfloat16 h0, l0, h1, l1;
                __nv_bfloat162 hp, lp;
                split2(v0.x, h0, l0); split2(v0.y, h1, l1);
                hp.x = h0; hp.y = h1; lp.x = l0; lp.y = l1;
                *reinterpret_cast<__nv_bfloat162*>(Ch + (size_t)r0 * c_ld + c0) = hp;
                *reinterpret_cast<__nv_bfloat162*>(Cl + (size_t)r0 * c_ld + c0) = lp;
                split2(v1.x, h0, l0); split2(v1.y, h1, l1);
                hp.x = h0; hp.y = h1; lp.x = l0; lp.y = l1;
                *reinterpret_cast<__nv_bfloat162*>(Ch + (size_t)(r0 + 8) * c_ld + c0) = hp;
                *reinterpret_cast<__nv_bfloat162*>(Cl + (size_t)(r0 + 8) * c_ld + c0) = lp;
            }
        }
    }
}

// ---------------------------------------------------------------------------
// Pre-pass: fp32 -> bf16 hi/lo split (one float4 per thread)
// ---------------------------------------------------------------------------
__global__ __launch_bounds__(256)
void split_kern(const float* __restrict__ X, __nv_bfloat16* __restrict__ H,
                __nv_bfloat16* __restrict__ L, int n4)
{
    int i = blockIdx.x * blockDim.x + threadIdx.x;
    if (i >= n4) return;
    float4 v = reinterpret_cast<const float4*>(X)[i];
    split4(H, L, (size_t)i * 4, v);
}

// ---------------------------------------------------------------------------
// Pre-pass: weight transpose + split. W[in=k][out=n] fp32 -> Wt[n][k] hi/lo.
// ---------------------------------------------------------------------------
__global__ __launch_bounds__(256)
void tsplit_kern(const float* __restrict__ W, __nv_bfloat16* __restrict__ TH,
                 __nv_bfloat16* __restrict__ TL)
{
    __shared__ float t[32][33];
    const int bx = blockIdx.x * 32;   // n
    const int by = blockIdx.y * 32;   // k
    const int x = threadIdx.x & 31;
    const int y = threadIdx.x >> 5;
#pragma unroll
    for (int i = 0; i < 4; i++)
        t[y + 8 * i][x] = W[(size_t)(by + y + 8 * i) * HID + bx + x];
    __syncthreads();
#pragma unroll
    for (int i = 0; i < 4; i++) {
        const int n = bx + y + 8 * i, k = by + x;
        __nv_bfloat16 h, l;
        split2(t[x][y + 8 * i], h, l);
        TH[(size_t)n * HID + k] = h;
        TL[(size_t)n * HID + k] = l;
    }
}

// ---------------------------------------------------------------------------
// Row softmax over N=2048; reads fp32 scores, writes bf16 hi/lo probs.
// ---------------------------------------------------------------------------
__device__ __forceinline__ float warp_max(float v) {
#pragma unroll
    for (int o = 16; o; o >>= 1) v = fmaxf(v, __shfl_xor_sync(0xFFFFFFFFu, v, o));
    return v;
}
__device__ __forceinline__ float warp_sum(float v) {
#pragma unroll
    for (int o = 16; o; o >>= 1) v += __shfl_xor_sync(0xFFFFFFFFu, v, o);
    return v;
}

__global__ __launch_bounds__(256)
void softmax_kern(const float* __restrict__ S, __nv_bfloat16* __restrict__ Ph,
                  __nv_bfloat16* __restrict__ Pl)
{
    const size_t row = blockIdx.x;
    const float* p = S + row * (size_t)SKV;
    const int tid = threadIdx.x;

    float4 v0 = *reinterpret_cast<const float4*>(p + tid * 4);
    float4 v1 = *reinterpret_cast<const float4*>(p + 1024 + tid * 4);

    float m = fmaxf(fmaxf(fmaxf(v0.x, v0.y), fmaxf(v0.z, v0.w)),
                    fmaxf(fmaxf(v1.x, v1.y), fmaxf(v1.z, v1.w)));

    __shared__ float red[8];
    float wm = warp_max(m);
    if ((tid & 31) == 0) red[tid >> 5] = wm;
    __syncthreads();
    float bm = red[0];
#pragma unroll
    for (int i = 1; i < 8; i++) bm = fmaxf(bm, red[i]);
    __syncthreads();

    v0.x = expf(v0.x - bm); v0.y = expf(v0.y - bm);
    v0.z = expf(v0.z - bm); v0.w = expf(v0.w - bm);
    v1.x = expf(v1.x - bm); v1.y = expf(v1.y - bm);
    v1.z = expf(v1.z - bm); v1.w = expf(v1.w - bm);

    float s = v0.x + v0.y + v0.z + v0.w + v1.x + v1.y + v1.z + v1.w;
    float ws = warp_sum(s);
    if ((tid & 31) == 0) red[tid >> 5] = ws;
    __syncthreads();
    float bs = 0.f;
#pragma unroll
    for (int i = 0; i < 8; i++) bs += red[i];

    const float inv = 1.f / bs;
    v0.x *= inv; v0.y *= inv; v0.z *= inv; v0.w *= inv;
    v1.x *= inv; v1.y *= inv; v1.z *= inv; v1.w *= inv;

    split4(Ph, Pl, row * (size_t)SKV + tid * 4, v0);
    split4(Ph, Pl, row * (size_t)SKV + 1024 + tid * 4, v1);
}

// ---------------------------------------------------------------------------
// Launch
// ---------------------------------------------------------------------------
extern "C" void kernel_launch(void* const* d_in, const int* in_sizes, int n_in,
                              void* d_out, int out_size)
{
    const float* Xq   = (const float*)d_in[0];
    const float* Xk   = (const float*)d_in[1];
    const float* mask = (const float*)d_in[2];
    const float* Wq   = (const float*)d_in[3];
    const float* bq   = (const float*)d_in[4];
    const float* Wk   = (const float*)d_in[5];
    const float* bk   = (const float*)d_in[6];
    const float* Wv   = (const float*)d_in[7];
    const float* bv   = (const float*)d_in[8];
    float* out = (float*)d_out;

    __nv_bfloat16 *Xqh, *Xql, *Xkh, *Xkl, *Wqth, *Wqtl, *Wkth, *Wktl, *Wvth, *Wvtl;
    __nv_bfloat16 *Qh, *Ql, *Kh, *Kl, *Vth, *Vtl, *Sh, *Sl;
    float* S;
    cudaGetSymbolAddress((void**)&Xqh, gXqh);   cudaGetSymbolAddress((void**)&Xql, gXql);
    cudaGetSymbolAddress((void**)&Xkh, gXkh);   cudaGetSymbolAddress((void**)&Xkl, gXkl);
    cudaGetSymbolAddress((void**)&Wqth, gWqth); cudaGetSymbolAddress((void**)&Wqtl, gWqtl);
    cudaGetSymbolAddress((void**)&Wkth, gWkth); cudaGetSymbolAddress((void**)&Wktl, gWktl);
    cudaGetSymbolAddress((void**)&Wvth, gWvth); cudaGetSymbolAddress((void**)&Wvtl, gWvtl);
    cudaGetSymbolAddress((void**)&Qh, gQh);     cudaGetSymbolAddress((void**)&Ql, gQl);
    cudaGetSymbolAddress((void**)&Kh, gKh);     cudaGetSymbolAddress((void**)&Kl, gKl);
    cudaGetSymbolAddress((void**)&Vth, gVth);   cudaGetSymbolAddress((void**)&Vtl, gVtl);
    cudaGetSymbolAddress((void**)&S, gS);
    cudaGetSymbolAddress((void**)&Sh, gSh);     cudaGetSymbolAddress((void**)&Sl, gSl);

    const float scale = 1.f / 32.f;   // 1/sqrt(1024)
    const int n4 = (int)(NX / 4);

    // Pre-pass: split inputs, transpose+split weights
    split_kern<<<(n4 + 255) / 256, 256>>>(Xq, Xqh, Xql, n4);
    split_kern<<<(n4 + 255) / 256, 256>>>(Xk, Xkh, Xkl, n4);
    tsplit_kern<<<dim3(32, 32), 256>>>(Wq, Wqth, Wqtl);
    tsplit_kern<<<dim3(32, 32), 256>>>(Wk, Wkth, Wktl);
    tsplit_kern<<<dim3(32, 32), 256>>>(Wv, Wvth, Wvtl);

    // Q = Xq @ Wq + bq  -> hi/lo, [B*Sq, H]
    gemm_bf<1><<<dim3(HID / 128, (BATCH * SQ) / 128, 1), 256>>>(
        Xqh, Xql, 0, HID, Wqth, Wqtl, 0, HID,
        nullptr, Qh, Ql, 0, HID, bq, 0, 1.f, HID);
    // K = Xk @ Wk + bk
    gemm_bf<1><<<dim3(HID / 128, (BATCH * SQ) / 128, 1), 256>>>(
        Xkh, Xkl, 0, HID, Wkth, Wktl, 0, HID,
        nullptr, Kh, Kl, 0, HID, bk, 0, 1.f, HID);
    // Vt = (Xk @ Wv + bv)^T : A = Wvt [H rows, K=H], B = Xk [B*Skv rows, K=H]
    gemm_bf<3><<<dim3((BATCH * SKV) / 128, HID / 128, 1), 256>>>(
        Wvth, Wvtl, 0, HID, Xkh, Xkl, 0, HID,
        nullptr, Vth, Vtl, 0, BATCH * SKV, bv, 0, 1.f, HID);
    // S = Q @ K^T * scale + mask  (fp32, batched)
    gemm_bf<2><<<dim3(SKV / 128, SQ / 128, BATCH), 256>>>(
        Qh, Ql, (size_t)SQ * HID, HID, Kh, Kl, (size_t)SKV * HID, HID,
        S, nullptr, nullptr, (size_t)SQ * SKV, SKV, mask, SKV, scale, HID);
    // softmax -> hi/lo probs
    softmax_kern<<<BATCH * SQ, 256>>>(S, Sh, Sl);
    // out = P @ V : A = P [Sq rows, K=Skv], B = Vt [H rows, K=Skv per batch]
    gemm_bf<0><<<dim3(HID / 128, SQ / 128, BATCH), 256>>>(
        Sh, Sl, (size_t)SQ * SKV, SKV, Vth, Vtl, (size_t)SKV, BATCH * SKV,
        out, nullptr, nullptr, (size_t)SQ * HID, HID, nullptr, 0, 1.f, SKV);
}

// round 10
// speedup vs baseline: 4.1782x; 1.2194x over previous
#include <cuda_runtime.h>
#include <cuda_fp16.h>
#include <stdint.h>
#include <math.h>

// Problem dims (fixed by reference setup_inputs)
#define BATCH 8
#define SQ    2048
#define SKV   2048
#define HID   1024

#define NX ((size_t)BATCH * SQ * HID)     // 16,777,216
#define NW ((size_t)HID * HID)            // 1,048,576
#define NS ((size_t)BATCH * SQ * SKV)     // 33,554,432

// ---------------------------------------------------------------------------
// Scratch (allocation-free rule: __device__ globals)
// ---------------------------------------------------------------------------
__device__ __half gXqh[NX], gXql[NX];      // Xq fp16 pair
__device__ __half gXkh[NX], gXkl[NX];      // Xk fp16 pair
__device__ __half gWqth[NW], gWqtl[NW];    // Wq^T pair
__device__ __half gWkth[NW], gWktl[NW];    // Wk^T pair
__device__ __half gWvt[NW];                // Wv^T single
__device__ __half gQh[NX], gQl[NX];        // Q pair
__device__ __half gKh[NX], gKl[NX];        // K pair
__device__ __half gVt[NX];                 // V^T single  [HID][BATCH*SKV]
__device__ float  gS[NS];                  // scores fp32
__device__ __half gSp[NS];                 // probs fp16 single

// ---------------------------------------------------------------------------
// helpers
// ---------------------------------------------------------------------------
__device__ __forceinline__ void split2h(float v, __half& h, __half& l) {
    h = __float2half_rn(v);
    l = __float2half_rn(v - __half2float(h));
}

__device__ __forceinline__ void split4h(__half* H, __half* L, size_t idx, float4 v) {
    __half h0, h1, h2, h3, l0, l1, l2, l3;
    split2h(v.x, h0, l0); split2h(v.y, h1, l1);
    split2h(v.z, h2, l2); split2h(v.w, h3, l3);
    *reinterpret_cast<__half2*>(H + idx)     = __halves2half2(h0, h1);
    *reinterpret_cast<__half2*>(H + idx + 2) = __halves2half2(h2, h3);
    *reinterpret_cast<__half2*>(L + idx)     = __halves2half2(l0, l1);
    *reinterpret_cast<__half2*>(L + idx + 2) = __halves2half2(l2, l3);
}

__device__ __forceinline__ void cvt4h(__half* P, size_t idx, float4 v) {
    *reinterpret_cast<__half2*>(P + idx)     = __halves2half2(__float2half_rn(v.x), __float2half_rn(v.y));
    *reinterpret_cast<__half2*>(P + idx + 2) = __halves2half2(__float2half_rn(v.z), __float2half_rn(v.w));
}

// mma.sync m16n8k16 fp16 -> fp32 accumulate
__device__ __forceinline__ void mma_f16(float* d, const uint32_t* a, const uint32_t* b) {
    asm volatile(
        "mma.sync.aligned.m16n8k16.row.col.f32.f16.f16.f32 "
        "{%0,%1,%2,%3}, {%4,%5,%6,%7}, {%8,%9}, {%0,%1,%2,%3};"
        : "+f"(d[0]), "+f"(d[1]), "+f"(d[2]), "+f"(d[3])
        : "r"(a[0]), "r"(a[1]), "r"(a[2]), "r"(a[3]),
          "r"(b[0]), "r"(b[1]));
}

// ---------------------------------------------------------------------------
// fp16 tensor-core GEMM: C[M,N] = A * B^T (+epilogue).
//   TERMS=3: A pair, B pair: ah*bh + ah*bl + al*bh  (21-bit effective)
//   TERMS=2: A single, B pair: a*bh + a*bl          (= a * b_full)
//   TERMS=1: A single, B single: a*b
// EPI: 0 plain fp32 | 1 +bias[n] -> fp16 PAIR out
//      2 scores: v*scale + (1-mask)*(-1e4), fp32 out
//      3 +bias[m] -> fp16 SINGLE out   (V^T)
// Block 128x128, BK=16, 256 threads = 8 warps (2x4), warp tile 64x32.
// Fragment-packed smem + conflict-free STS.128 staging (validated R9 layout).
// ---------------------------------------------------------------------------
template<int TERMS, int EPI>
__global__ __launch_bounds__(256)
void gemm_f16(const __half* __restrict__ Agh, const __half* __restrict__ Agl,
              size_t a_bs, int a_rs,
              const __half* __restrict__ Bgh, const __half* __restrict__ Bgl,
              size_t b_bs, int b_rs,
              float* __restrict__ Cf, __half* __restrict__ Ch, __half* __restrict__ Cl,
              size_t c_bs, int c_ld,
              const float* __restrict__ E, int e_s, float scale, int K)
{
    __shared__ uint32_t sm[2][4][1024];   // [stage][Ah,Al,Bh,Bl][word]  32 KB

    const int tid  = threadIdx.x;
    const int wid  = tid >> 5;
    const int lane = tid & 31;
    const int g  = lane >> 2;
    const int tg = lane & 3;
    const int bz = blockIdx.z;
    const int bm = blockIdx.y * 128;
    const int bn = blockIdx.x * 128;
    const int wm = (wid >> 2) * 64;
    const int wn = (wid & 3) * 32;

    const __half* Ah = Agh + (size_t)bz * a_bs;
    const __half* Al = (TERMS == 3) ? (Agl + (size_t)bz * a_bs) : nullptr;
    const __half* Bh = Bgh + (size_t)bz * b_bs;
    const __half* Bl = (TERMS >= 2) ? (Bgl + (size_t)bz * b_bs) : nullptr;

    // ---- staging indices (A side): 4 words contiguous -> STS.128 ----
    const int ablk = tid >> 5;
    const int amm  = (tid & 31) >> 2;
    const int app  = tid & 3;
    const int aword = ablk * 128 + (tid & 31) * 4;
    const size_t a00 = (size_t)(bm + ablk * 16 + amm) * a_rs + 2 * app;
    const size_t a10 = a00 + (size_t)8 * a_rs;
    // ---- staging indices (B side) ----
    const int bnb = tid >> 4;
    const int bnn = (tid & 15) >> 1;
    const int bj  = tid & 1;
    const int bword = bnb * 64 + bnn * 8 + bj * 4;
    const size_t b00 = (size_t)(bn + bnb * 8 + bnn) * b_rs + 4 * bj;

    uint32_t Rah0, Rah1, Rah2, Rah3, Ral0, Ral1, Ral2, Ral3;
    uint2 Rbh0, Rbh1, Rbl0, Rbl1;

    auto loadR = [&](int c) {
        const size_t k = (size_t)c << 4;
        Rah0 = *reinterpret_cast<const uint32_t*>(Ah + a00 + k);
        Rah1 = *reinterpret_cast<const uint32_t*>(Ah + a10 + k);
        Rah2 = *reinterpret_cast<const uint32_t*>(Ah + a00 + k + 8);
        Rah3 = *reinterpret_cast<const uint32_t*>(Ah + a10 + k + 8);
        if (TERMS == 3) {
            Ral0 = *reinterpret_cast<const uint32_t*>(Al + a00 + k);
            Ral1 = *reinterpret_cast<const uint32_t*>(Al + a10 + k);
            Ral2 = *reinterpret_cast<const uint32_t*>(Al + a00 + k + 8);
            Ral3 = *reinterpret_cast<const uint32_t*>(Al + a10 + k + 8);
        }
        Rbh0 = *reinterpret_cast<const uint2*>(Bh + b00 + k);
        Rbh1 = *reinterpret_cast<const uint2*>(Bh + b00 + k + 8);
        if (TERMS >= 2) {
            Rbl0 = *reinterpret_cast<const uint2*>(Bl + b00 + k);
            Rbl1 = *reinterpret_cast<const uint2*>(Bl + b00 + k + 8);
        }
    };
    auto storeR = [&](int buf) {
        *reinterpret_cast<uint4*>(&sm[buf][0][aword]) = make_uint4(Rah0, Rah1, Rah2, Rah3);
        if (TERMS == 3)
            *reinterpret_cast<uint4*>(&sm[buf][1][aword]) = make_uint4(Ral0, Ral1, Ral2, Ral3);
        *reinterpret_cast<uint4*>(&sm[buf][2][bword]) = make_uint4(Rbh0.x, Rbh1.x, Rbh0.y, Rbh1.y);
        if (TERMS >= 2)
            *reinterpret_cast<uint4*>(&sm[buf][3][bword]) = make_uint4(Rbl0.x, Rbl1.x, Rbl0.y, Rbl1.y);
    };

    float acc[4][4][4];
#pragma unroll
    for (int mt = 0; mt < 4; mt++)
#pragma unroll
        for (int nt = 0; nt < 4; nt++)
#pragma unroll
            for (int q = 0; q < 4; q++) acc[mt][nt][q] = 0.f;

    const int NCH = K >> 4;

    loadR(0); storeR(0);
    loadR(1);
    __syncthreads();

    for (int c = 0; c < NCH; c++) {
        const int st = c & 1;
        if (c + 1 < NCH) storeR(st ^ 1);
        if (c + 2 < NCH) loadR(c + 2);

        // B-hi fragments
        uint32_t bh[4][2];
#pragma unroll
        for (int nt = 0; nt < 4; nt++) {
            const int bbase = (((wn >> 3) + nt) << 6) + lane * 2;
            uint2 h2 = *reinterpret_cast<const uint2*>(&sm[st][2][bbase]);
            bh[nt][0] = h2.x; bh[nt][1] = h2.y;
        }
        // A-hi fragments
        uint32_t af[4][4];
#pragma unroll
        for (int mt = 0; mt < 4; mt++) {
            const int abase = (((wm >> 4) + mt) << 7) + lane * 4;
            uint4 h4 = *reinterpret_cast<const uint4*>(&sm[st][0][abase]);
            af[mt][0] = h4.x; af[mt][1] = h4.y; af[mt][2] = h4.z; af[mt][3] = h4.w;
        }

        // term 0: a(h) * b(h)
#pragma unroll
        for (int mt = 0; mt < 4; mt++)
#pragma unroll
            for (int nt = 0; nt < 4; nt++)
                mma_f16(acc[mt][nt], af[mt], bh[nt]);

        if (TERMS >= 2) {
            // term 1: a(h) * bl
            uint32_t bl[4][2];
#pragma unroll
            for (int nt = 0; nt < 4; nt++) {
                const int bbase = (((wn >> 3) + nt) << 6) + lane * 2;
                uint2 l2 = *reinterpret_cast<const uint2*>(&sm[st][3][bbase]);
                bl[nt][0] = l2.x; bl[nt][1] = l2.y;
            }
#pragma unroll
            for (int mt = 0; mt < 4; mt++)
#pragma unroll
                for (int nt = 0; nt < 4; nt++)
                    mma_f16(acc[mt][nt], af[mt], bl[nt]);
        }

        if (TERMS == 3) {
            // term 2: al * bh
#pragma unroll
            for (int mt = 0; mt < 4; mt++) {
                const int abase = (((wm >> 4) + mt) << 7) + lane * 4;
                uint4 l4 = *reinterpret_cast<const uint4*>(&sm[st][1][abase]);
                af[mt][0] = l4.x; af[mt][1] = l4.y; af[mt][2] = l4.z; af[mt][3] = l4.w;
            }
#pragma unroll
            for (int mt = 0; mt < 4; mt++)
#pragma unroll
                for (int nt = 0; nt < 4; nt++)
                    mma_f16(acc[mt][nt], af[mt], bh[nt]);
        }

        if (c + 1 < NCH) __syncthreads();
    }

    // ---- epilogue ----
#pragma unroll
    for (int mt = 0; mt < 4; mt++) {
        const int r0 = bm + wm + mt * 16 + g;
#pragma unroll
        for (int nt = 0; nt < 4; nt++) {
            const int c0 = bn + wn + nt * 8 + 2 * tg;
            float2 v0 = make_float2(acc[mt][nt][0], acc[mt][nt][1]);   // row r0
            float2 v1 = make_float2(acc[mt][nt][2], acc[mt][nt][3]);   // row r0+8
            if (EPI == 0 || EPI == 2) {
                if (EPI == 2) {
                    const float* mk = E + (size_t)bz * e_s;
                    const float q0 = (1.f - mk[c0])     * -10000.f;
                    const float q1 = (1.f - mk[c0 + 1]) * -10000.f;
                    v0.x = v0.x * scale + q0;  v0.y = v0.y * scale + q1;
                    v1.x = v1.x * scale + q0;  v1.y = v1.y * scale + q1;
                }
                float* Cb = Cf + (size_t)bz * c_bs;
                *reinterpret_cast<float2*>(Cb + (size_t)r0 * c_ld + c0)       = v0;
                *reinterpret_cast<float2*>(Cb + (size_t)(r0 + 8) * c_ld + c0) = v1;
            } else if (EPI == 1) {
                v0.x += E[c0]; v0.y += E[c0 + 1];
                v1.x += E[c0]; v1.y += E[c0 + 1];
                __half h0, l0, h1, l1;
                split2h(v0.x, h0, l0); split2h(v0.y, h1, l1);
                *reinterpret_cast<__half2*>(Ch + (size_t)r0 * c_ld + c0) = __halves2half2(h0, h1);
                *reinterpret_cast<__half2*>(Cl + (size_t)r0 * c_ld + c0) = __halves2half2(l0, l1);
                split2h(v1.x, h0, l0); split2h(v1.y, h1, l1);
                *reinterpret_cast<__half2*>(Ch + (size_t)(r0 + 8) * c_ld + c0) = __halves2half2(h0, h1);
                *reinterpret_cast<__half2*>(Cl + (size_t)(r0 + 8) * c_ld + c0) = __halves2half2(l0, l1);
            } else {  // EPI == 3: row bias, single fp16 out
                v0.x += E[r0];     v0.y += E[r0];
                v1.x += E[r0 + 8]; v1.y += E[r0 + 8];
                *reinterpret_cast<__half2*>(Ch + (size_t)r0 * c_ld + c0) =
                    __halves2half2(__float2half_rn(v0.x), __float2half_rn(v0.y));
                *reinterpret_cast<__half2*>(Ch + (size_t)(r0 + 8) * c_ld + c0) =
                    __halves2half2(__float2half_rn(v1.x), __float2half_rn(v1.y));
            }
        }
    }
}

// ---------------------------------------------------------------------------
// Pre-pass: fp32 -> fp16 hi/lo split (one float4 per thread)
// ---------------------------------------------------------------------------
__global__ __launch_bounds__(256)
void split_kern(const float* __restrict__ X, __half* __restrict__ H,
                __half* __restrict__ L, int n4)
{
    int i = blockIdx.x * blockDim.x + threadIdx.x;
    if (i >= n4) return;
    float4 v = reinterpret_cast<const float4*>(X)[i];
    split4h(H, L, (size_t)i * 4, v);
}

// ---------------------------------------------------------------------------
// Pre-pass: weight transpose + split (pair) or convert (single).
// W[in=k][out=n] fp32 -> Wt[n][k].
// ---------------------------------------------------------------------------
template<bool PAIR>
__global__ __launch_bounds__(256)
void tsplit_kern(const float* __restrict__ W, __half* __restrict__ TH,
                 __half* __restrict__ TL)
{
    __shared__ float t[32][33];
    const int bx = blockIdx.x * 32;   // n
    const int by = blockIdx.y * 32;   // k
    const int x = threadIdx.x & 31;
    const int y = threadIdx.x >> 5;
#pragma unroll
    for (int i = 0; i < 4; i++)
        t[y + 8 * i][x] = W[(size_t)(by + y + 8 * i) * HID + bx + x];
    __syncthreads();
#pragma unroll
    for (int i = 0; i < 4; i++) {
        const int n = bx + y + 8 * i, k = by + x;
        if (PAIR) {
            __half h, l;
            split2h(t[x][y + 8 * i], h, l);
            TH[(size_t)n * HID + k] = h;
            TL[(size_t)n * HID + k] = l;
        } else {
            TH[(size_t)n * HID + k] = __float2half_rn(t[x][y + 8 * i]);
        }
    }
}

// ---------------------------------------------------------------------------
// Row softmax over N=2048; reads fp32 scores, writes fp16 single probs.
// ---------------------------------------------------------------------------
__device__ __forceinline__ float warp_max(float v) {
#pragma unroll
    for (int o = 16; o; o >>= 1) v = fmaxf(v, __shfl_xor_sync(0xFFFFFFFFu, v, o));
    return v;
}
__device__ __forceinline__ float warp_sum(float v) {
#pragma unroll
    for (int o = 16; o; o >>= 1) v += __shfl_xor_sync(0xFFFFFFFFu, v, o);
    return v;
}

__global__ __launch_bounds__(256)
void softmax_kern(const float* __restrict__ S, __half* __restrict__ P)
{
    const size_t row = blockIdx.x;
    const float* p = S + row * (size_t)SKV;
    const int tid = threadIdx.x;

    float4 v0 = *reinterpret_cast<const float4*>(p + tid * 4);
    float4 v1 = *reinterpret_cast<const float4*>(p + 1024 + tid * 4);

    float m = fmaxf(fmaxf(fmaxf(v0.x, v0.y), fmaxf(v0.z, v0.w)),
                    fmaxf(fmaxf(v1.x, v1.y), fmaxf(v1.z, v1.w)));

    __shared__ float red[8];
    float wm = warp_max(m);
    if ((tid & 31) == 0) red[tid >> 5] = wm;
    __syncthreads();
    float bm = red[0];
#pragma unroll
    for (int i = 1; i < 8; i++) bm = fmaxf(bm, red[i]);
    __syncthreads();

    v0.x = expf(v0.x - bm); v0.y = expf(v0.y - bm);
    v0.z = expf(v0.z - bm); v0.w = expf(v0.w - bm);
    v1.x = expf(v1.x - bm); v1.y = expf(v1.y - bm);
    v1.z = expf(v1.z - bm); v1.w = expf(v1.w - bm);

    float s = v0.x + v0.y + v0.z + v0.w + v1.x + v1.y + v1.z + v1.w;
    float ws = warp_sum(s);
    if ((tid & 31) == 0) red[tid >> 5] = ws;
    __syncthreads();
    float bs = 0.f;
#pragma unroll
    for (int i = 0; i < 8; i++) bs += red[i];

    const float inv = 1.f / bs;
    v0.x *= inv; v0.y *= inv; v0.z *= inv; v0.w *= inv;
    v1.x *= inv; v1.y *= inv; v1.z *= inv; v1.w *= inv;

    cvt4h(P, row * (size_t)SKV + tid * 4, v0);
    cvt4h(P, row * (size_t)SKV + 1024 + tid * 4, v1);
}

// ---------------------------------------------------------------------------
// Launch
// ---------------------------------------------------------------------------
extern "C" void kernel_launch(void* const* d_in, const int* in_sizes, int n_in,
                              void* d_out, int out_size)
{
    const float* Xq   = (const float*)d_in[0];
    const float* Xk   = (const float*)d_in[1];
    const float* mask = (const float*)d_in[2];
    const float* Wq   = (const float*)d_in[3];
    const float* bq   = (const float*)d_in[4];
    const float* Wk   = (const float*)d_in[5];
    const float* bk   = (const float*)d_in[6];
    const float* Wv   = (const float*)d_in[7];
    const float* bv   = (const float*)d_in[8];
    float* out = (float*)d_out;

    __half *Xqh, *Xql, *Xkh, *Xkl, *Wqth, *Wqtl, *Wkth, *Wktl, *Wvt;
    __half *Qh, *Ql, *Kh, *Kl, *Vt, *Sp;
    float* S;
    cudaGetSymbolAddress((void**)&Xqh, gXqh);   cudaGetSymbolAddress((void**)&Xql, gXql);
    cudaGetSymbolAddress((void**)&Xkh, gXkh);   cudaGetSymbolAddress((void**)&Xkl, gXkl);
    cudaGetSymbolAddress((void**)&Wqth, gWqth); cudaGetSymbolAddress((void**)&Wqtl, gWqtl);
    cudaGetSymbolAddress((void**)&Wkth, gWkth); cudaGetSymbolAddress((void**)&Wktl, gWktl);
    cudaGetSymbolAddress((void**)&Wvt, gWvt);
    cudaGetSymbolAddress((void**)&Qh, gQh);     cudaGetSymbolAddress((void**)&Ql, gQl);
    cudaGetSymbolAddress((void**)&Kh, gKh);     cudaGetSymbolAddress((void**)&Kl, gKl);
    cudaGetSymbolAddress((void**)&Vt, gVt);
    cudaGetSymbolAddress((void**)&S, gS);
    cudaGetSymbolAddress((void**)&Sp, gSp);

    const float scale = 1.f / 32.f;   // 1/sqrt(1024)
    const int n4 = (int)(NX / 4);

    // Pre-pass
    split_kern<<<(n4 + 255) / 256, 256>>>(Xq, Xqh, Xql, n4);
    split_kern<<<(n4 + 255) / 256, 256>>>(Xk, Xkh, Xkl, n4);
    tsplit_kern<true ><<<dim3(32, 32), 256>>>(Wq, Wqth, Wqtl);
    tsplit_kern<true ><<<dim3(32, 32), 256>>>(Wk, Wkth, Wktl);
    tsplit_kern<false><<<dim3(32, 32), 256>>>(Wv, Wvt, nullptr);

    // Q = Xq @ Wq + bq  (3-term, pair out)
    gemm_f16<3, 1><<<dim3(HID / 128, (BATCH * SQ) / 128, 1), 256>>>(
        Xqh, Xql, 0, HID, Wqth, Wqtl, 0, HID,
        nullptr, Qh, Ql, 0, HID, bq, 0, 1.f, HID);
    // K = Xk @ Wk + bk  (3-term, pair out)
    gemm_f16<3, 1><<<dim3(HID / 128, (BATCH * SQ) / 128, 1), 256>>>(
        Xkh, Xkl, 0, HID, Wkth, Wktl, 0, HID,
        nullptr, Kh, Kl, 0, HID, bk, 0, 1.f, HID);
    // Vt = (Xk @ Wv + bv)^T  (2-term: A = Wvt single, B = Xk pair; single out)
    gemm_f16<2, 3><<<dim3((BATCH * SKV) / 128, HID / 128, 1), 256>>>(
        Wvt, nullptr, 0, HID, Xkh, Xkl, 0, HID,
        nullptr, Vt, nullptr, 0, BATCH * SKV, bv, 0, 1.f, HID);
    // S = Q @ K^T * scale + mask  (3-term, fp32 out)
    gemm_f16<3, 2><<<dim3(SKV / 128, SQ / 128, BATCH), 256>>>(
        Qh, Ql, (size_t)SQ * HID, HID, Kh, Kl, (size_t)SKV * HID, HID,
        S, nullptr, nullptr, (size_t)SQ * SKV, SKV, mask, SKV, scale, HID);
    // softmax -> fp16 single probs
    softmax_kern<<<BATCH * SQ, 256>>>(S, Sp);
    // out = P @ V  (1-term: A = Sp single, B = Vt single)
    gemm_f16<1, 0><<<dim3(HID / 128, SQ / 128, BATCH), 256>>>(
        Sp, nullptr, (size_t)SQ * SKV, SKV, Vt, nullptr, (size_t)SKV, BATCH * SKV,
        out, nullptr, nullptr, (size_t)SQ * HID, HID, nullptr, 0, 1.f, SKV);
}

// round 11
// speedup vs baseline: 4.7067x; 1.1265x over previous
#include <cuda_runtime.h>
#include <cuda_fp16.h>
#include <stdint.h>
#include <math.h>

// Problem dims (fixed by reference setup_inputs)
#define BATCH 8
#define SQ    2048
#define SKV   2048
#define HID   1024

#define NX ((size_t)BATCH * SQ * HID)     // 16,777,216
#define NW ((size_t)HID * HID)            // 1,048,576
#define NS ((size_t)BATCH * SQ * SKV)     // 33,554,432

// ---------------------------------------------------------------------------
// Scratch (allocation-free rule: __device__ globals)
// ---------------------------------------------------------------------------
__device__ __half gXqh[NX], gXql[NX];      // Xq fp16 pair
__device__ __half gXkh[NX], gXkl[NX];      // Xk fp16 pair
__device__ __half gWqth[NW], gWqtl[NW];    // Wq^T pair
__device__ __half gWkth[NW], gWktl[NW];    // Wk^T pair
__device__ __half gWvt[NW];                // Wv^T single
__device__ __half gQh[NX], gQl[NX];        // Q pair
__device__ __half gK1[NX];                 // K single
__device__ __half gVt[NX];                 // V^T single  [HID][BATCH*SKV]
__device__ float  gS[NS];                  // scores fp32
__device__ __half gSp[NS];                 // probs fp16 single

// ---------------------------------------------------------------------------
// helpers
// ---------------------------------------------------------------------------
__device__ __forceinline__ void split2h(float v, __half& h, __half& l) {
    h = __float2half_rn(v);
    l = __float2half_rn(v - __half2float(h));
}

__device__ __forceinline__ void split4h(__half* H, __half* L, size_t idx, float4 v) {
    __half h0, h1, h2, h3, l0, l1, l2, l3;
    split2h(v.x, h0, l0); split2h(v.y, h1, l1);
    split2h(v.z, h2, l2); split2h(v.w, h3, l3);
    *reinterpret_cast<__half2*>(H + idx)     = __halves2half2(h0, h1);
    *reinterpret_cast<__half2*>(H + idx + 2) = __halves2half2(h2, h3);
    *reinterpret_cast<__half2*>(L + idx)     = __halves2half2(l0, l1);
    *reinterpret_cast<__half2*>(L + idx + 2) = __halves2half2(l2, l3);
}

__device__ __forceinline__ void cvt4h(__half* P, size_t idx, float4 v) {
    *reinterpret_cast<__half2*>(P + idx)     = __halves2half2(__float2half_rn(v.x), __float2half_rn(v.y));
    *reinterpret_cast<__half2*>(P + idx + 2) = __halves2half2(__float2half_rn(v.z), __float2half_rn(v.w));
}

// mma.sync m16n8k16 fp16 -> fp32 accumulate
__device__ __forceinline__ void mma_f16(float* d, const uint32_t* a, const uint32_t* b) {
    asm volatile(
        "mma.sync.aligned.m16n8k16.row.col.f32.f16.f16.f32 "
        "{%0,%1,%2,%3}, {%4,%5,%6,%7}, {%8,%9}, {%0,%1,%2,%3};"
        : "+f"(d[0]), "+f"(d[1]), "+f"(d[2]), "+f"(d[3])
        : "r"(a[0]), "r"(a[1]), "r"(a[2]), "r"(a[3]),
          "r"(b[0]), "r"(b[1]));
}

// ---------------------------------------------------------------------------
// fp16 tensor-core GEMM: C[M,N] = A * B^T (+epilogue).
//   TERMS=3: A pair,  B pair  : ah*bh + ah*bl + al*bh
//   TERMS=2: A single,B pair  : a*bh + a*bl
//   TERMS=4: A pair,  B single: ah*b + al*b
//   TERMS=1: A single,B single: a*b
// EPI: 0 plain fp32 | 1 +bias[n] -> fp16 PAIR out
//      2 scores: v*scale + (1-mask)*(-1e4), fp32 out
//      3 +bias[m] -> fp16 SINGLE out | 4 +bias[n] -> fp16 SINGLE out
// Block 128x128, BK=16, 256 threads = 8 warps (2x4), warp tile 64x32.
// Fragment-packed smem + conflict-free STS.128 staging (validated R9 layout).
// ---------------------------------------------------------------------------
#define NEED_AL (TERMS == 3 || TERMS == 4)
#define NEED_BL (TERMS == 3 || TERMS == 2)

template<int TERMS, int EPI>
__global__ __launch_bounds__(256, 2)
void gemm_f16(const __half* __restrict__ Agh, const __half* __restrict__ Agl,
              size_t a_bs, int a_rs,
              const __half* __restrict__ Bgh, const __half* __restrict__ Bgl,
              size_t b_bs, int b_rs,
              float* __restrict__ Cf, __half* __restrict__ Ch, __half* __restrict__ Cl,
              size_t c_bs, int c_ld,
              const float* __restrict__ E, int e_s, float scale, int K)
{
    __shared__ uint32_t sm[2][4][1024];   // [stage][Ah,Al,Bh,Bl][word]  32 KB

    const int tid  = threadIdx.x;
    const int wid  = tid >> 5;
    const int lane = tid & 31;
    const int g  = lane >> 2;
    const int tg = lane & 3;
    const int bz = blockIdx.z;
    const int bm = blockIdx.y * 128;
    const int bn = blockIdx.x * 128;
    const int wm = (wid >> 2) * 64;
    const int wn = (wid & 3) * 32;

    const __half* Ah = Agh + (size_t)bz * a_bs;
    const __half* Al = NEED_AL ? (Agl + (size_t)bz * a_bs) : nullptr;
    const __half* Bh = Bgh + (size_t)bz * b_bs;
    const __half* Bl = NEED_BL ? (Bgl + (size_t)bz * b_bs) : nullptr;

    // ---- staging indices (A side): 4 words contiguous -> STS.128 ----
    const int ablk = tid >> 5;
    const int amm  = (tid & 31) >> 2;
    const int app  = tid & 3;
    const int aword = ablk * 128 + (tid & 31) * 4;
    const size_t a00 = (size_t)(bm + ablk * 16 + amm) * a_rs + 2 * app;
    const size_t a10 = a00 + (size_t)8 * a_rs;
    // ---- staging indices (B side) ----
    const int bnb = tid >> 4;
    const int bnn = (tid & 15) >> 1;
    const int bj  = tid & 1;
    const int bword = bnb * 64 + bnn * 8 + bj * 4;
    const size_t b00 = (size_t)(bn + bnb * 8 + bnn) * b_rs + 4 * bj;

    uint32_t Rah0, Rah1, Rah2, Rah3, Ral0, Ral1, Ral2, Ral3;
    uint2 Rbh0, Rbh1, Rbl0, Rbl1;

    auto loadR = [&](int c) {
        const size_t k = (size_t)c << 4;
        Rah0 = *reinterpret_cast<const uint32_t*>(Ah + a00 + k);
        Rah1 = *reinterpret_cast<const uint32_t*>(Ah + a10 + k);
        Rah2 = *reinterpret_cast<const uint32_t*>(Ah + a00 + k + 8);
        Rah3 = *reinterpret_cast<const uint32_t*>(Ah + a10 + k + 8);
        if (NEED_AL) {
            Ral0 = *reinterpret_cast<const uint32_t*>(Al + a00 + k);
            Ral1 = *reinterpret_cast<const uint32_t*>(Al + a10 + k);
            Ral2 = *reinterpret_cast<const uint32_t*>(Al + a00 + k + 8);
            Ral3 = *reinterpret_cast<const uint32_t*>(Al + a10 + k + 8);
        }
        Rbh0 = *reinterpret_cast<const uint2*>(Bh + b00 + k);
        Rbh1 = *reinterpret_cast<const uint2*>(Bh + b00 + k + 8);
        if (NEED_BL) {
            Rbl0 = *reinterpret_cast<const uint2*>(Bl + b00 + k);
            Rbl1 = *reinterpret_cast<const uint2*>(Bl + b00 + k + 8);
        }
    };
    auto storeR = [&](int buf) {
        *reinterpret_cast<uint4*>(&sm[buf][0][aword]) = make_uint4(Rah0, Rah1, Rah2, Rah3);
        if (NEED_AL)
            *reinterpret_cast<uint4*>(&sm[buf][1][aword]) = make_uint4(Ral0, Ral1, Ral2, Ral3);
        *reinterpret_cast<uint4*>(&sm[buf][2][bword]) = make_uint4(Rbh0.x, Rbh1.x, Rbh0.y, Rbh1.y);
        if (NEED_BL)
            *reinterpret_cast<uint4*>(&sm[buf][3][bword]) = make_uint4(Rbl0.x, Rbl1.x, Rbl0.y, Rbl1.y);
    };

    float acc[4][4][4];
#pragma unroll
    for (int mt = 0; mt < 4; mt++)
#pragma unroll
        for (int nt = 0; nt < 4; nt++)
#pragma unroll
            for (int q = 0; q < 4; q++) acc[mt][nt][q] = 0.f;

    const int NCH = K >> 4;

    loadR(0); storeR(0);
    loadR(1);
    __syncthreads();

    for (int c = 0; c < NCH; c++) {
        const int st = c & 1;
        if (c + 1 < NCH) storeR(st ^ 1);
        if (c + 2 < NCH) loadR(c + 2);

        // B-hi fragments
        uint32_t bh[4][2];
#pragma unroll
        for (int nt = 0; nt < 4; nt++) {
            const int bbase = (((wn >> 3) + nt) << 6) + lane * 2;
            uint2 h2 = *reinterpret_cast<const uint2*>(&sm[st][2][bbase]);
            bh[nt][0] = h2.x; bh[nt][1] = h2.y;
        }
        // A-hi fragments
        uint32_t af[4][4];
#pragma unroll
        for (int mt = 0; mt < 4; mt++) {
            const int abase = (((wm >> 4) + mt) << 7) + lane * 4;
            uint4 h4 = *reinterpret_cast<const uint4*>(&sm[st][0][abase]);
            af[mt][0] = h4.x; af[mt][1] = h4.y; af[mt][2] = h4.z; af[mt][3] = h4.w;
        }

        // term 0: a(h) * b(h)
#pragma unroll
        for (int mt = 0; mt < 4; mt++)
#pragma unroll
            for (int nt = 0; nt < 4; nt++)
                mma_f16(acc[mt][nt], af[mt], bh[nt]);

        if (NEED_BL) {
            // term: a(h) * bl
            uint32_t bl[4][2];
#pragma unroll
            for (int nt = 0; nt < 4; nt++) {
                const int bbase = (((wn >> 3) + nt) << 6) + lane * 2;
                uint2 l2 = *reinterpret_cast<const uint2*>(&sm[st][3][bbase]);
                bl[nt][0] = l2.x; bl[nt][1] = l2.y;
            }
#pragma unroll
            for (int mt = 0; mt < 4; mt++)
#pragma unroll
                for (int nt = 0; nt < 4; nt++)
                    mma_f16(acc[mt][nt], af[mt], bl[nt]);
        }

        if (NEED_AL) {
            // term: al * b(h)
#pragma unroll
            for (int mt = 0; mt < 4; mt++) {
                const int abase = (((wm >> 4) + mt) << 7) + lane * 4;
                uint4 l4 = *reinterpret_cast<const uint4*>(&sm[st][1][abase]);
                af[mt][0] = l4.x; af[mt][1] = l4.y; af[mt][2] = l4.z; af[mt][3] = l4.w;
            }
#pragma unroll
            for (int mt = 0; mt < 4; mt++)
#pragma unroll
                for (int nt = 0; nt < 4; nt++)
                    mma_f16(acc[mt][nt], af[mt], bh[nt]);
        }

        if (c + 1 < NCH) __syncthreads();
    }

    // ---- epilogue ----
#pragma unroll
    for (int mt = 0; mt < 4; mt++) {
        const int r0 = bm + wm + mt * 16 + g;
#pragma unroll
        for (int nt = 0; nt < 4; nt++) {
            const int c0 = bn + wn + nt * 8 + 2 * tg;
            float2 v0 = make_float2(acc[mt][nt][0], acc[mt][nt][1]);   // row r0
            float2 v1 = make_float2(acc[mt][nt][2], acc[mt][nt][3]);   // row r0+8
            if (EPI == 0 || EPI == 2) {
                if (EPI == 2) {
                    const float* mk = E + (size_t)bz * e_s;
                    const float q0 = (1.f - mk[c0])     * -10000.f;
                    const float q1 = (1.f - mk[c0 + 1]) * -10000.f;
                    v0.x = v0.x * scale + q0;  v0.y = v0.y * scale + q1;
                    v1.x = v1.x * scale + q0;  v1.y = v1.y * scale + q1;
                }
                float* Cb = Cf + (size_t)bz * c_bs;
                *reinterpret_cast<float2*>(Cb + (size_t)r0 * c_ld + c0)       = v0;
                *reinterpret_cast<float2*>(Cb + (size_t)(r0 + 8) * c_ld + c0) = v1;
            } else if (EPI == 1) {
                v0.x += E[c0]; v0.y += E[c0 + 1];
                v1.x += E[c0]; v1.y += E[c0 + 1];
                __half h0, l0, h1, l1;
                split2h(v0.x, h0, l0); split2h(v0.y, h1, l1);
                *reinterpret_cast<__half2*>(Ch + (size_t)r0 * c_ld + c0) = __halves2half2(h0, h1);
                *reinterpret_cast<__half2*>(Cl + (size_t)r0 * c_ld + c0) = __halves2half2(l0, l1);
                split2h(v1.x, h0, l0); split2h(v1.y, h1, l1);
                *reinterpret_cast<__half2*>(Ch + (size_t)(r0 + 8) * c_ld + c0) = __halves2half2(h0, h1);
                *reinterpret_cast<__half2*>(Cl + (size_t)(r0 + 8) * c_ld + c0) = __halves2half2(l0, l1);
            } else {
                // EPI 3: +bias[m], single out.  EPI 4: +bias[n], single out.
                if (EPI == 3) {
                    v0.x += E[r0];     v0.y += E[r0];
                    v1.x += E[r0 + 8]; v1.y += E[r0 + 8];
                } else {
                    v0.x += E[c0]; v0.y += E[c0 + 1];
                    v1.x += E[c0]; v1.y += E[c0 + 1];
                }
                *reinterpret_cast<__half2*>(Ch + (size_t)r0 * c_ld + c0) =
                    __halves2half2(__float2half_rn(v0.x), __float2half_rn(v0.y));
                *reinterpret_cast<__half2*>(Ch + (size_t)(r0 + 8) * c_ld + c0) =
                    __halves2half2(__float2half_rn(v1.x), __float2half_rn(v1.y));
            }
        }
    }
}

// ---------------------------------------------------------------------------
// Pre-pass: fp32 -> fp16 hi/lo split (one float4 per thread)
// ---------------------------------------------------------------------------
__global__ __launch_bounds__(256)
void split_kern(const float* __restrict__ X, __half* __restrict__ H,
                __half* __restrict__ L, int n4)
{
    int i = blockIdx.x * blockDim.x + threadIdx.x;
    if (i >= n4) return;
    float4 v = reinterpret_cast<const float4*>(X)[i];
    split4h(H, L, (size_t)i * 4, v);
}

// ---------------------------------------------------------------------------
// Pre-pass: weight transpose + split (pair) or convert (single).
// ---------------------------------------------------------------------------
template<bool PAIR>
__global__ __launch_bounds__(256)
void tsplit_kern(const float* __restrict__ W, __half* __restrict__ TH,
                 __half* __restrict__ TL)
{
    __shared__ float t[32][33];
    const int bx = blockIdx.x * 32;   // n
    const int by = blockIdx.y * 32;   // k
    const int x = threadIdx.x & 31;
    const int y = threadIdx.x >> 5;
#pragma unroll
    for (int i = 0; i < 4; i++)
        t[y + 8 * i][x] = W[(size_t)(by + y + 8 * i) * HID + bx + x];
    __syncthreads();
#pragma unroll
    for (int i = 0; i < 4; i++) {
        const int n = bx + y + 8 * i, k = by + x;
        if (PAIR) {
            __half h, l;
            split2h(t[x][y + 8 * i], h, l);
            TH[(size_t)n * HID + k] = h;
            TL[(size_t)n * HID + k] = l;
        } else {
            TH[(size_t)n * HID + k] = __float2half_rn(t[x][y + 8 * i]);
        }
    }
}

// ---------------------------------------------------------------------------
// Row softmax over N=2048; reads fp32 scores, writes fp16 single probs.
// ---------------------------------------------------------------------------
__device__ __forceinline__ float warp_max(float v) {
#pragma unroll
    for (int o = 16; o; o >>= 1) v = fmaxf(v, __shfl_xor_sync(0xFFFFFFFFu, v, o));
    return v;
}
__device__ __forceinline__ float warp_sum(float v) {
#pragma unroll
    for (int o = 16; o; o >>= 1) v += __shfl_xor_sync(0xFFFFFFFFu, v, o);
    return v;
}

__global__ __launch_bounds__(256)
void softmax_kern(const float* __restrict__ S, __half* __restrict__ P)
{
    const size_t row = blockIdx.x;
    const float* p = S + row * (size_t)SKV;
    const int tid = threadIdx.x;

    float4 v0 = *reinterpret_cast<const float4*>(p + tid * 4);
    float4 v1 = *reinterpret_cast<const float4*>(p + 1024 + tid * 4);

    float m = fmaxf(fmaxf(fmaxf(v0.x, v0.y), fmaxf(v0.z, v0.w)),
                    fmaxf(fmaxf(v1.x, v1.y), fmaxf(v1.z, v1.w)));

    __shared__ float red[8];
    float wm = warp_max(m);
    if ((tid & 31) == 0) red[tid >> 5] = wm;
    __syncthreads();
    float bm = red[0];
#pragma unroll
    for (int i = 1; i < 8; i++) bm = fmaxf(bm, red[i]);
    __syncthreads();

    v0.x = expf(v0.x - bm); v0.y = expf(v0.y - bm);
    v0.z = expf(v0.z - bm); v0.w = expf(v0.w - bm);
    v1.x = expf(v1.x - bm); v1.y = expf(v1.y - bm);
    v1.z = expf(v1.z - bm); v1.w = expf(v1.w - bm);

    float s = v0.x + v0.y + v0.z + v0.w + v1.x + v1.y + v1.z + v1.w;
    float ws = warp_sum(s);
    if ((tid & 31) == 0) red[tid >> 5] = ws;
    __syncthreads();
    float bs = 0.f;
#pragma unroll
    for (int i = 0; i < 8; i++) bs += red[i];

    const float inv = 1.f / bs;
    v0.x *= inv; v0.y *= inv; v0.z *= inv; v0.w *= inv;
    v1.x *= inv; v1.y *= inv; v1.z *= inv; v1.w *= inv;

    cvt4h(P, row * (size_t)SKV + tid * 4, v0);
    cvt4h(P, row * (size_t)SKV + 1024 + tid * 4, v1);
}

// ---------------------------------------------------------------------------
// Launch
// ---------------------------------------------------------------------------
extern "C" void kernel_launch(void* const* d_in, const int* in_sizes, int n_in,
                              void* d_out, int out_size)
{
    const float* Xq   = (const float*)d_in[0];
    const float* Xk   = (const float*)d_in[1];
    const float* mask = (const float*)d_in[2];
    const float* Wq   = (const float*)d_in[3];
    const float* bq   = (const float*)d_in[4];
    const float* Wk   = (const float*)d_in[5];
    const float* bk   = (const float*)d_in[6];
    const float* Wv   = (const float*)d_in[7];
    const float* bv   = (const float*)d_in[8];
    float* out = (float*)d_out;

    __half *Xqh, *Xql, *Xkh, *Xkl, *Wqth, *Wqtl, *Wkth, *Wktl, *Wvt;
    __half *Qh, *Ql, *K1, *Vt, *Sp;
    float* S;
    cudaGetSymbolAddress((void**)&Xqh, gXqh);   cudaGetSymbolAddress((void**)&Xql, gXql);
    cudaGetSymbolAddress((void**)&Xkh, gXkh);   cudaGetSymbolAddress((void**)&Xkl, gXkl);
    cudaGetSymbolAddress((void**)&Wqth, gWqth); cudaGetSymbolAddress((void**)&Wqtl, gWqtl);
    cudaGetSymbolAddress((void**)&Wkth, gWkth); cudaGetSymbolAddress((void**)&Wktl, gWktl);
    cudaGetSymbolAddress((void**)&Wvt, gWvt);
    cudaGetSymbolAddress((void**)&Qh, gQh);     cudaGetSymbolAddress((void**)&Ql, gQl);
    cudaGetSymbolAddress((void**)&K1, gK1);
    cudaGetSymbolAddress((void**)&Vt, gVt);
    cudaGetSymbolAddress((void**)&S, gS);
    cudaGetSymbolAddress((void**)&Sp, gSp);

    const float scale = 1.f / 32.f;   // 1/sqrt(1024)
    const int n4 = (int)(NX / 4);

    // Pre-pass
    split_kern<<<(n4 + 255) / 256, 256>>>(Xq, Xqh, Xql, n4);
    split_kern<<<(n4 + 255) / 256, 256>>>(Xk, Xkh, Xkl, n4);
    tsplit_kern<true ><<<dim3(32, 32), 256>>>(Wq, Wqth, Wqtl);
    tsplit_kern<true ><<<dim3(32, 32), 256>>>(Wk, Wkth, Wktl);
    tsplit_kern<false><<<dim3(32, 32), 256>>>(Wv, Wvt, nullptr);

    // Q = Xq @ Wq + bq  (3-term, pair out)
    gemm_f16<3, 1><<<dim3(HID / 128, (BATCH * SQ) / 128, 1), 256>>>(
        Xqh, Xql, 0, HID, Wqth, Wqtl, 0, HID,
        nullptr, Qh, Ql, 0, HID, bq, 0, 1.f, HID);
    // K = Xk @ Wk + bk  (3-term compute, SINGLE fp16 out)
    gemm_f16<3, 4><<<dim3(HID / 128, (BATCH * SQ) / 128, 1), 256>>>(
        Xkh, Xkl, 0, HID, Wkth, Wktl, 0, HID,
        nullptr, K1, nullptr, 0, HID, bk, 0, 1.f, HID);
    // Vt = (Xk @ Wv + bv)^T  (2-term: A = Wvt single, B = Xk pair; single out)
    gemm_f16<2, 3><<<dim3((BATCH * SKV) / 128, HID / 128, 1), 256>>>(
        Wvt, nullptr, 0, HID, Xkh, Xkl, 0, HID,
        nullptr, Vt, nullptr, 0, BATCH * SKV, bv, 0, 1.f, HID);
    // S = Q @ K^T * scale + mask  (2-term: A = Q pair, B = K single; fp32 out)
    gemm_f16<4, 2><<<dim3(SKV / 128, SQ / 128, BATCH), 256>>>(
        Qh, Ql, (size_t)SQ * HID, HID, K1, nullptr, (size_t)SKV * HID, HID,
        S, nullptr, nullptr, (size_t)SQ * SKV, SKV, mask, SKV, scale, HID);
    // softmax -> fp16 single probs
    softmax_kern<<<BATCH * SQ, 256>>>(S, Sp);
    // out = P @ V  (1-term: A = Sp single, B = Vt single)
    gemm_f16<1, 0><<<dim3(HID / 128, SQ / 128, BATCH), 256>>>(
        Sp, nullptr, (size_t)SQ * SKV, SKV, Vt, nullptr, (size_t)SKV, BATCH * SKV,
        out, nullptr, nullptr, (size_t)SQ * HID, HID, nullptr, 0, 1.f, SKV);
}

// round 13
// speedup vs baseline: 6.1124x; 1.2987x over previous
#include <cuda_runtime.h>
#include <cuda_fp16.h>
#include <stdint.h>
#include <math.h>

// Problem dims (fixed by reference setup_inputs)
#define BATCH 8
#define SQ    2048
#define SKV   2048
#define HID   1024

#define NX ((size_t)BATCH * SQ * HID)     // 16,777,216
#define NW ((size_t)HID * HID)            // 1,048,576
#define NS ((size_t)BATCH * SQ * SKV)     // 33,554,432

// ---------------------------------------------------------------------------
// Scratch (allocation-free rule: __device__ globals)
// ---------------------------------------------------------------------------
__device__ __half gXq1[NX];                // Xq fp16 single
__device__ __half gXk1[NX];                // Xk fp16 single
__device__ __half gWqth[NW], gWqtl[NW];    // Wq^T pair
__device__ __half gWkth[NW], gWktl[NW];    // Wk^T pair
__device__ __half gWvt[NW];                // Wv^T single
__device__ __half gQ1[NX];                 // Q single
__device__ __half gK1[NX];                 // K single
__device__ __half gVt[NX];                 // V^T single  [HID][BATCH*SKV]
__device__ float  gS[NS];                  // scores fp32
__device__ __half gSp[NS];                 // probs fp16 single

// ---------------------------------------------------------------------------
// helpers
// ---------------------------------------------------------------------------
__device__ __forceinline__ void split2h(float v, __half& h, __half& l) {
    h = __float2half_rn(v);
    l = __float2half_rn(v - __half2float(h));
}

__device__ __forceinline__ void cvt4h(__half* P, size_t idx, float4 v) {
    *reinterpret_cast<__half2*>(P + idx)     = __halves2half2(__float2half_rn(v.x), __float2half_rn(v.y));
    *reinterpret_cast<__half2*>(P + idx + 2) = __halves2half2(__float2half_rn(v.z), __float2half_rn(v.w));
}

// mma.sync m16n8k16 fp16 -> fp32 accumulate
__device__ __forceinline__ void mma_f16(float* d, const uint32_t* a, const uint32_t* b) {
    asm volatile(
        "mma.sync.aligned.m16n8k16.row.col.f32.f16.f16.f32 "
        "{%0,%1,%2,%3}, {%4,%5,%6,%7}, {%8,%9}, {%0,%1,%2,%3};"
        : "+f"(d[0]), "+f"(d[1]), "+f"(d[2]), "+f"(d[3])
        : "r"(a[0]), "r"(a[1]), "r"(a[2]), "r"(a[3]),
          "r"(b[0]), "r"(b[1]));
}

// ---------------------------------------------------------------------------
// fp16 tensor-core GEMM: C[M,N] = A * B^T (+epilogue).
//   TERMS=3: A pair,  B pair  : ah*bh + ah*bl + al*bh
//   TERMS=2: A single,B pair  : a*bh + a*bl
//   TERMS=4: A pair,  B single: ah*b + al*b
//   TERMS=1: A single,B single: a*b
// EPI: 0 plain fp32 | 1 +bias[n] -> fp16 PAIR out
//      2 scores: v*scale + (1-mask)*(-1e4), fp32 out
//      3 +bias[m] -> fp16 SINGLE out | 4 +bias[n] -> fp16 SINGLE out
// Block 128x128, BK=16, 256 threads = 8 warps (2x4), warp tile 64x32.
// Fragment-packed smem + conflict-free STS.128 staging (validated layout).
// ---------------------------------------------------------------------------
#define NEED_AL (TERMS == 3 || TERMS == 4)
#define NEED_BL (TERMS == 3 || TERMS == 2)

template<int TERMS, int EPI>
__global__ __launch_bounds__(256, 2)
void gemm_f16(const __half* __restrict__ Agh, const __half* __restrict__ Agl,
              size_t a_bs, int a_rs,
              const __half* __restrict__ Bgh, const __half* __restrict__ Bgl,
              size_t b_bs, int b_rs,
              float* __restrict__ Cf, __half* __restrict__ Ch, __half* __restrict__ Cl,
              size_t c_bs, int c_ld,
              const float* __restrict__ E, int e_s, float scale, int K)
{
    __shared__ uint32_t sm[2][4][1024];   // [stage][Ah,Al,Bh,Bl][word]  32 KB

    const int tid  = threadIdx.x;
    const int wid  = tid >> 5;
    const int lane = tid & 31;
    const int g  = lane >> 2;
    const int tg = lane & 3;
    const int bz = blockIdx.z;
    const int bm = blockIdx.y * 128;
    const int bn = blockIdx.x * 128;
    const int wm = (wid >> 2) * 64;
    const int wn = (wid & 3) * 32;

    const __half* Ah = Agh + (size_t)bz * a_bs;
    const __half* Al = NEED_AL ? (Agl + (size_t)bz * a_bs) : nullptr;
    const __half* Bh = Bgh + (size_t)bz * b_bs;
    const __half* Bl = NEED_BL ? (Bgl + (size_t)bz * b_bs) : nullptr;

    // ---- staging indices (A side): 4 words contiguous -> STS.128 ----
    const int ablk = tid >> 5;
    const int amm  = (tid & 31) >> 2;
    const int app  = tid & 3;
    const int aword = ablk * 128 + (tid & 31) * 4;
    const size_t a00 = (size_t)(bm + ablk * 16 + amm) * a_rs + 2 * app;
    const size_t a10 = a00 + (size_t)8 * a_rs;
    // ---- staging indices (B side) ----
    const int bnb = tid >> 4;
    const int bnn = (tid & 15) >> 1;
    const int bj  = tid & 1;
    const int bword = bnb * 64 + bnn * 8 + bj * 4;
    const size_t b00 = (size_t)(bn + bnb * 8 + bnn) * b_rs + 4 * bj;

    uint32_t Rah0, Rah1, Rah2, Rah3, Ral0, Ral1, Ral2, Ral3;
    uint2 Rbh0, Rbh1, Rbl0, Rbl1;

    auto loadR = [&](int c) {
        const size_t k = (size_t)c << 4;
        Rah0 = *reinterpret_cast<const uint32_t*>(Ah + a00 + k);
        Rah1 = *reinterpret_cast<const uint32_t*>(Ah + a10 + k);
        Rah2 = *reinterpret_cast<const uint32_t*>(Ah + a00 + k + 8);
        Rah3 = *reinterpret_cast<const uint32_t*>(Ah + a10 + k + 8);
        if (NEED_AL) {
            Ral0 = *reinterpret_cast<const uint32_t*>(Al + a00 + k);
            Ral1 = *reinterpret_cast<const uint32_t*>(Al + a10 + k);
            Ral2 = *reinterpret_cast<const uint32_t*>(Al + a00 + k + 8);
            Ral3 = *reinterpret_cast<const uint32_t*>(Al + a10 + k + 8);
        }
        Rbh0 = *reinterpret_cast<const uint2*>(Bh + b00 + k);
        Rbh1 = *reinterpret_cast<const uint2*>(Bh + b00 + k + 8);
        if (NEED_BL) {
            Rbl0 = *reinterpret_cast<const uint2*>(Bl + b00 + k);
            Rbl1 = *reinterpret_cast<const uint2*>(Bl + b00 + k + 8);
        }
    };
    auto storeR = [&](int buf) {
        *reinterpret_cast<uint4*>(&sm[buf][0][aword]) = make_uint4(Rah0, Rah1, Rah2, Rah3);
        if (NEED_AL)
            *reinterpret_cast<uint4*>(&sm[buf][1][aword]) = make_uint4(Ral0, Ral1, Ral2, Ral3);
        *reinterpret_cast<uint4*>(&sm[buf][2][bword]) = make_uint4(Rbh0.x, Rbh1.x, Rbh0.y, Rbh1.y);
        if (NEED_BL)
            *reinterpret_cast<uint4*>(&sm[buf][3][bword]) = make_uint4(Rbl0.x, Rbl1.x, Rbl0.y, Rbl1.y);
    };

    float acc[4][4][4];
#pragma unroll
    for (int mt = 0; mt < 4; mt++)
#pragma unroll
        for (int nt = 0; nt < 4; nt++)
#pragma unroll
            for (int q = 0; q < 4; q++) acc[mt][nt][q] = 0.f;

    const int NCH = K >> 4;

    loadR(0); storeR(0);
    loadR(1);
    __syncthreads();

    for (int c = 0; c < NCH; c++) {
        const int st = c & 1;
        if (c + 1 < NCH) storeR(st ^ 1);
        if (c + 2 < NCH) loadR(c + 2);

        // B-hi fragments
        uint32_t bh[4][2];
#pragma unroll
        for (int nt = 0; nt < 4; nt++) {
            const int bbase = (((wn >> 3) + nt) << 6) + lane * 2;
            uint2 h2 = *reinterpret_cast<const uint2*>(&sm[st][2][bbase]);
            bh[nt][0] = h2.x; bh[nt][1] = h2.y;
        }
        // A-hi fragments
        uint32_t af[4][4];
#pragma unroll
        for (int mt = 0; mt < 4; mt++) {
            const int abase = (((wm >> 4) + mt) << 7) + lane * 4;
            uint4 h4 = *reinterpret_cast<const uint4*>(&sm[st][0][abase]);
            af[mt][0] = h4.x; af[mt][1] = h4.y; af[mt][2] = h4.z; af[mt][3] = h4.w;
        }

        // term 0: a(h) * b(h)
#pragma unroll
        for (int mt = 0; mt < 4; mt++)
#pragma unroll
            for (int nt = 0; nt < 4; nt++)
                mma_f16(acc[mt][nt], af[mt], bh[nt]);

        if (NEED_BL) {
            // term: a(h) * bl
            uint32_t bl[4][2];
#pragma unroll
            for (int nt = 0; nt < 4; nt++) {
                const int bbase = (((wn >> 3) + nt) << 6) + lane * 2;
                uint2 l2 = *reinterpret_cast<const uint2*>(&sm[st][3][bbase]);
                bl[nt][0] = l2.x; bl[nt][1] = l2.y;
            }
#pragma unroll
            for (int mt = 0; mt < 4; mt++)
#pragma unroll
                for (int nt = 0; nt < 4; nt++)
                    mma_f16(acc[mt][nt], af[mt], bl[nt]);
        }

        if (NEED_AL) {
            // term: al * b(h)
#pragma unroll
            for (int mt = 0; mt < 4; mt++) {
                const int abase = (((wm >> 4) + mt) << 7) + lane * 4;
                uint4 l4 = *reinterpret_cast<const uint4*>(&sm[st][1][abase]);
                af[mt][0] = l4.x; af[mt][1] = l4.y; af[mt][2] = l4.z; af[mt][3] = l4.w;
            }
#pragma unroll
            for (int mt = 0; mt < 4; mt++)
#pragma unroll
                for (int nt = 0; nt < 4; nt++)
                    mma_f16(acc[mt][nt], af[mt], bh[nt]);
        }

        if (c + 1 < NCH) __syncthreads();
    }

    // ---- epilogue ----
#pragma unroll
    for (int mt = 0; mt < 4; mt++) {
        const int r0 = bm + wm + mt * 16 + g;
#pragma unroll
        for (int nt = 0; nt < 4; nt++) {
            const int c0 = bn + wn + nt * 8 + 2 * tg;
            float2 v0 = make_float2(acc[mt][nt][0], acc[mt][nt][1]);   // row r0
            float2 v1 = make_float2(acc[mt][nt][2], acc[mt][nt][3]);   // row r0+8
            if (EPI == 0 || EPI == 2) {
                if (EPI == 2) {
                    const float* mk = E + (size_t)bz * e_s;
                    const float q0 = (1.f - mk[c0])     * -10000.f;
                    const float q1 = (1.f - mk[c0 + 1]) * -10000.f;
                    v0.x = v0.x * scale + q0;  v0.y = v0.y * scale + q1;
                    v1.x = v1.x * scale + q0;  v1.y = v1.y * scale + q1;
                }
                float* Cb = Cf + (size_t)bz * c_bs;
                *reinterpret_cast<float2*>(Cb + (size_t)r0 * c_ld + c0)       = v0;
                *reinterpret_cast<float2*>(Cb + (size_t)(r0 + 8) * c_ld + c0) = v1;
            } else if (EPI == 1) {
                v0.x += E[c0]; v0.y += E[c0 + 1];
                v1.x += E[c0]; v1.y += E[c0 + 1];
                __half h0, l0, h1, l1;
                split2h(v0.x, h0, l0); split2h(v0.y, h1, l1);
                *reinterpret_cast<__half2*>(Ch + (size_t)r0 * c_ld + c0) = __halves2half2(h0, h1);
                *reinterpret_cast<__half2*>(Cl + (size_t)r0 * c_ld + c0) = __halves2half2(l0, l1);
                split2h(v1.x, h0, l0); split2h(v1.y, h1, l1);
                *reinterpret_cast<__half2*>(Ch + (size_t)(r0 + 8) * c_ld + c0) = __halves2half2(h0, h1);
                *reinterpret_cast<__half2*>(Cl + (size_t)(r0 + 8) * c_ld + c0) = __halves2half2(l0, l1);
            } else {
                // EPI 3: +bias[m], single out.  EPI 4: +bias[n], single out.
                if (EPI == 3) {
                    v0.x += E[r0];     v0.y += E[r0];
                    v1.x += E[r0 + 8]; v1.y += E[r0 + 8];
                } else {
                    v0.x += E[c0]; v0.y += E[c0 + 1];
                    v1.x += E[c0]; v1.y += E[c0 + 1];
                }
                *reinterpret_cast<__half2*>(Ch + (size_t)r0 * c_ld + c0) =
                    __halves2half2(__float2half_rn(v0.x), __float2half_rn(v0.y));
                *reinterpret_cast<__half2*>(Ch + (size_t)(r0 + 8) * c_ld + c0) =
                    __halves2half2(__float2half_rn(v1.x), __float2half_rn(v1.y));
            }
        }
    }
}

// ---------------------------------------------------------------------------
// Pre-pass: fp32 -> fp16 single convert (one float4 per thread)
// ---------------------------------------------------------------------------
__global__ __launch_bounds__(256)
void cvt_kern(const float* __restrict__ X, __half* __restrict__ H, int n4)
{
    int i = blockIdx.x * blockDim.x + threadIdx.x;
    if (i >= n4) return;
    float4 v = reinterpret_cast<const float4*>(X)[i];
    cvt4h(H, (size_t)i * 4, v);
}

// ---------------------------------------------------------------------------
// Pre-pass: weight transpose + split (pair) or convert (single).
// ---------------------------------------------------------------------------
template<bool PAIR>
__global__ __launch_bounds__(256)
void tsplit_kern(const float* __restrict__ W, __half* __restrict__ TH,
                 __half* __restrict__ TL)
{
    __shared__ float t[32][33];
    const int bx = blockIdx.x * 32;   // n
    const int by = blockIdx.y * 32;   // k
    const int x = threadIdx.x & 31;
    const int y = threadIdx.x >> 5;
#pragma unroll
    for (int i = 0; i < 4; i++)
        t[y + 8 * i][x] = W[(size_t)(by + y + 8 * i) * HID + bx + x];
    __syncthreads();
#pragma unroll
    for (int i = 0; i < 4; i++) {
        const int n = bx + y + 8 * i, k = by + x;
        if (PAIR) {
            __half h, l;
            split2h(t[x][y + 8 * i], h, l);
            TH[(size_t)n * HID + k] = h;
            TL[(size_t)n * HID + k] = l;
        } else {
            TH[(size_t)n * HID + k] = __float2half_rn(t[x][y + 8 * i]);
        }
    }
}

// ---------------------------------------------------------------------------
// Row softmax over N=2048; reads fp32 scores, writes fp16 single probs.
// ---------------------------------------------------------------------------
__device__ __forceinline__ float warp_max(float v) {
#pragma unroll
    for (int o = 16; o; o >>= 1) v = fmaxf(v, __shfl_xor_sync(0xFFFFFFFFu, v, o));
    return v;
}
__device__ __forceinline__ float warp_sum(float v) {
#pragma unroll
    for (int o = 16; o; o >>= 1) v += __shfl_xor_sync(0xFFFFFFFFu, v, o);
    return v;
}

__global__ __launch_bounds__(256)
void softmax_kern(const float* __restrict__ S, __half* __restrict__ P)
{
    const size_t row = blockIdx.x;
    const float* p = S + row * (size_t)SKV;
    const int tid = threadIdx.x;

    float4 v0 = *reinterpret_cast<const float4*>(p + tid * 4);
    float4 v1 = *reinterpret_cast<const float4*>(p + 1024 + tid * 4);

    float m = fmaxf(fmaxf(fmaxf(v0.x, v0.y), fmaxf(v0.z, v0.w)),
                    fmaxf(fmaxf(v1.x, v1.y), fmaxf(v1.z, v1.w)));

    __shared__ float red[8];
    float wm = warp_max(m);
    if ((tid & 31) == 0) red[tid >> 5] = wm;
    __syncthreads();
    float bm = red[0];
#pragma unroll
    for (int i = 1; i < 8; i++) bm = fmaxf(bm, red[i]);
    __syncthreads();

    v0.x = expf(v0.x - bm); v0.y = expf(v0.y - bm);
    v0.z = expf(v0.z - bm); v0.w = expf(v0.w - bm);
    v1.x = expf(v1.x - bm); v1.y = expf(v1.y - bm);
    v1.z = expf(v1.z - bm); v1.w = expf(v1.w - bm);

    float s = v0.x + v0.y + v0.z + v0.w + v1.x + v1.y + v1.z + v1.w;
    float ws = warp_sum(s);
    if ((tid & 31) == 0) red[tid >> 5] = ws;
    __syncthreads();
    float bs = 0.f;
#pragma unroll
    for (int i = 0; i < 8; i++) bs += red[i];

    const float inv = 1.f / bs;
    v0.x *= inv; v0.y *= inv; v0.z *= inv; v0.w *= inv;
    v1.x *= inv; v1.y *= inv; v1.z *= inv; v1.w *= inv;

    cvt4h(P, row * (size_t)SKV + tid * 4, v0);
    cvt4h(P, row * (size_t)SKV + 1024 + tid * 4, v1);
}

// ---------------------------------------------------------------------------
// Launch
// ---------------------------------------------------------------------------
extern "C" void kernel_launch(void* const* d_in, const int* in_sizes, int n_in,
                              void* d_out, int out_size)
{
    const float* Xq   = (const float*)d_in[0];
    const float* Xk   = (const float*)d_in[1];
    const float* mask = (const float*)d_in[2];
    const float* Wq   = (const float*)d_in[3];
    const float* bq   = (const float*)d_in[4];
    const float* Wk   = (const float*)d_in[5];
    const float* bk   = (const float*)d_in[6];
    const float* Wv   = (const float*)d_in[7];
    const float* bv   = (const float*)d_in[8];
    float* out = (float*)d_out;

    __half *Xq1, *Xk1, *Wqth, *Wqtl, *Wkth, *Wktl, *Wvt;
    __half *Q1, *K1, *Vt, *Sp;
    float* S;
    cudaGetSymbolAddress((void**)&Xq1, gXq1);
    cudaGetSymbolAddress((void**)&Xk1, gXk1);
    cudaGetSymbolAddress((void**)&Wqth, gWqth); cudaGetSymbolAddress((void**)&Wqtl, gWqtl);
    cudaGetSymbolAddress((void**)&Wkth, gWkth); cudaGetSymbolAddress((void**)&Wktl, gWktl);
    cudaGetSymbolAddress((void**)&Wvt, gWvt);
    cudaGetSymbolAddress((void**)&Q1, gQ1);
    cudaGetSymbolAddress((void**)&K1, gK1);
    cudaGetSymbolAddress((void**)&Vt, gVt);
    cudaGetSymbolAddress((void**)&S, gS);
    cudaGetSymbolAddress((void**)&Sp, gSp);

    const float scale = 1.f / 32.f;   // 1/sqrt(1024)
    const int n4 = (int)(NX / 4);

    // Pre-pass: convert inputs to single fp16; weights Wq/Wk pair, Wv single
    cvt_kern<<<(n4 + 255) / 256, 256>>>(Xq, Xq1, n4);
    cvt_kern<<<(n4 + 255) / 256, 256>>>(Xk, Xk1, n4);
    tsplit_kern<true ><<<dim3(32, 32), 256>>>(Wq, Wqth, Wqtl);
    tsplit_kern<true ><<<dim3(32, 32), 256>>>(Wk, Wkth, Wktl);
    tsplit_kern<false><<<dim3(32, 32), 256>>>(Wv, Wvt, nullptr);

    // Q = Xq @ Wq + bq  (2-term: Xq single x Wq pair; single out)
    gemm_f16<2, 4><<<dim3(HID / 128, (BATCH * SQ) / 128, 1), 256>>>(
        Xq1, nullptr, 0, HID, Wqth, Wqtl, 0, HID,
        nullptr, Q1, nullptr, 0, HID, bq, 0, 1.f, HID);
    // K = Xk @ Wk + bk  (2-term; single out)
    gemm_f16<2, 4><<<dim3(HID / 128, (BATCH * SQ) / 128, 1), 256>>>(
        Xk1, nullptr, 0, HID, Wkth, Wktl, 0, HID,
        nullptr, K1, nullptr, 0, HID, bk, 0, 1.f, HID);
    // Vt = (Xk @ Wv + bv)^T  (1-term: Wvt single x Xk single; single out, bias[m])
    gemm_f16<1, 3><<<dim3((BATCH * SKV) / 128, HID / 128, 1), 256>>>(
        Wvt, nullptr, 0, HID, Xk1, nullptr, 0, HID,
        nullptr, Vt, nullptr, 0, BATCH * SKV, bv, 0, 1.f, HID);
    // S = Q @ K^T * scale + mask  (1-term: Q single x K single; fp32 out)
    gemm_f16<1, 2><<<dim3(SKV / 128, SQ / 128, BATCH), 256>>>(
        Q1, nullptr, (size_t)SQ * HID, HID, K1, nullptr, (size_t)SKV * HID, HID,
        S, nullptr, nullptr, (size_t)SQ * SKV, SKV, mask, SKV, scale, HID);
    // softmax -> fp16 single probs
    softmax_kern<<<BATCH * SQ, 256>>>(S, Sp);
    // out = P @ V  (1-term)
    gemm_f16<1, 0><<<dim3(HID / 128, SQ / 128, BATCH), 256>>>(
        Sp, nullptr, (size_t)SQ * SKV, SKV, Vt, nullptr, (size_t)SKV, BATCH * SKV,
        out, nullptr, nullptr, (size_t)SQ * HID, HID, nullptr, 0, 1.f, SKV);
}

// round 14
// speedup vs baseline: 6.2781x; 1.0271x over previous
#include <cuda_runtime.h>
#include <cuda_fp16.h>
#include <stdint.h>
#include <math.h>

// Problem dims (fixed by reference setup_inputs)
#define BATCH 8
#define SQ    2048
#define SKV   2048
#define HID   1024

#define NX ((size_t)BATCH * SQ * HID)     // 16,777,216
#define NW ((size_t)HID * HID)            // 1,048,576
#define NS ((size_t)BATCH * SQ * SKV)     // 33,554,432

// ---------------------------------------------------------------------------
// Scratch (allocation-free rule: __device__ globals)
// ---------------------------------------------------------------------------
__device__ __half gXq1[NX];                // Xq fp16 single
__device__ __half gXk1[NX];                // Xk fp16 single
__device__ __half gWqth[NW], gWqtl[NW];    // Wq^T pair
__device__ __half gWkth[NW], gWktl[NW];    // Wk^T pair
__device__ __half gWvt[NW];                // Wv^T single
__device__ __half gQ1[NX];                 // Q single
__device__ __half gK1[NX];                 // K single
__device__ __half gVt[NX];                 // V^T single  [HID][BATCH*SKV]
__device__ float  gS[NS];                  // scores fp32
__device__ __half gSp[NS];                 // probs fp16 single

// ---------------------------------------------------------------------------
// helpers
// ---------------------------------------------------------------------------
__device__ __forceinline__ void split2h(float v, __half& h, __half& l) {
    h = __float2half_rn(v);
    l = __float2half_rn(v - __half2float(h));
}

__device__ __forceinline__ void cvt4h(__half* P, size_t idx, float4 v) {
    *reinterpret_cast<__half2*>(P + idx)     = __halves2half2(__float2half_rn(v.x), __float2half_rn(v.y));
    *reinterpret_cast<__half2*>(P + idx + 2) = __halves2half2(__float2half_rn(v.z), __float2half_rn(v.w));
}

// mma.sync m16n8k16 fp16 -> fp32 accumulate
__device__ __forceinline__ void mma_f16(float* d, const uint32_t* a, const uint32_t* b) {
    asm volatile(
        "mma.sync.aligned.m16n8k16.row.col.f32.f16.f16.f32 "
        "{%0,%1,%2,%3}, {%4,%5,%6,%7}, {%8,%9}, {%0,%1,%2,%3};"
        : "+f"(d[0]), "+f"(d[1]), "+f"(d[2]), "+f"(d[3])
        : "r"(a[0]), "r"(a[1]), "r"(a[2]), "r"(a[3]),
          "r"(b[0]), "r"(b[1]));
}

// ---------------------------------------------------------------------------
// fp16 tensor-core GEMM: C[M,N] = A * B^T (+epilogue). A always fp16 single.
//   TERMS=2: B pair  : a*bh + a*bl      TERMS=1: B single: a*b
// EPI: 0 plain fp32 | 2 scores: v*scale + (1-mask)*(-1e4), fp32 out
//      3 +bias[m] -> fp16 single | 4 +bias[n] -> fp16 single
// Block 128x128, BK=32 (two 16-k sub-stages), 256 threads = 8 warps (2x4),
// warp tile 64x32. Fragment-packed smem, conflict-free STS.128 staging;
// one __syncthreads per 32-k chunk. Smem 48KB static -> 2 CTAs/SM.
// ---------------------------------------------------------------------------
template<int TERMS, int EPI>
__global__ __launch_bounds__(256, 2)
void gemm_f16(const __half* __restrict__ Ag, size_t a_bs, int a_rs,
              const __half* __restrict__ Bgh, const __half* __restrict__ Bgl,
              size_t b_bs, int b_rs,
              float* __restrict__ Cf, __half* __restrict__ Ch,
              size_t c_bs, int c_ld,
              const float* __restrict__ E, int e_s, float scale, int K)
{
    __shared__ uint32_t sm[2][3][2048];   // [stage][A,Bh,Bl][word]  48 KB

    const int tid  = threadIdx.x;
    const int wid  = tid >> 5;
    const int lane = tid & 31;
    const int g  = lane >> 2;
    const int tg = lane & 3;
    const int bz = blockIdx.z;
    const int bm = blockIdx.y * 128;
    const int bn = blockIdx.x * 128;
    const int wm = (wid >> 2) * 64;
    const int wn = (wid & 3) * 32;

    const __half* Ah = Ag  + (size_t)bz * a_bs;
    const __half* Bh = Bgh + (size_t)bz * b_bs;
    const __half* Bl = (TERMS == 2) ? (Bgl + (size_t)bz * b_bs) : nullptr;

    // ---- staging indices (validated layout, per 16-k sub-stage) ----
    const int ablk = tid >> 5;
    const int amm  = (tid & 31) >> 2;
    const int app  = tid & 3;
    const int aword = ablk * 128 + (tid & 31) * 4;
    const size_t a00 = (size_t)(bm + ablk * 16 + amm) * a_rs + 2 * app;
    const size_t a10 = a00 + (size_t)8 * a_rs;
    const int bnb = tid >> 4;
    const int bnn = (tid & 15) >> 1;
    const int bj  = tid & 1;
    const int bword = bnb * 64 + bnn * 8 + bj * 4;
    const size_t b00 = (size_t)(bn + bnb * 8 + bnn) * b_rs + 4 * bj;

    // prefetch registers: one 32-k chunk
    uint32_t Ra[8];
    uint2 Rbh[4], Rbl[4];

    auto loadR = [&](int c) {
#pragma unroll
        for (int s = 0; s < 2; s++) {
            const size_t k = ((size_t)c << 5) + (s << 4);
            Ra[s * 4 + 0] = *reinterpret_cast<const uint32_t*>(Ah + a00 + k);
            Ra[s * 4 + 1] = *reinterpret_cast<const uint32_t*>(Ah + a10 + k);
            Ra[s * 4 + 2] = *reinterpret_cast<const uint32_t*>(Ah + a00 + k + 8);
            Ra[s * 4 + 3] = *reinterpret_cast<const uint32_t*>(Ah + a10 + k + 8);
            Rbh[s * 2 + 0] = *reinterpret_cast<const uint2*>(Bh + b00 + k);
            Rbh[s * 2 + 1] = *reinterpret_cast<const uint2*>(Bh + b00 + k + 8);
            if (TERMS == 2) {
                Rbl[s * 2 + 0] = *reinterpret_cast<const uint2*>(Bl + b00 + k);
                Rbl[s * 2 + 1] = *reinterpret_cast<const uint2*>(Bl + b00 + k + 8);
            }
        }
    };
    auto storeR = [&](int buf) {
#pragma unroll
        for (int s = 0; s < 2; s++) {
            const int off = s * 1024;
            *reinterpret_cast<uint4*>(&sm[buf][0][aword + off]) =
                make_uint4(Ra[s*4+0], Ra[s*4+1], Ra[s*4+2], Ra[s*4+3]);
            *reinterpret_cast<uint4*>(&sm[buf][1][bword + off]) =
                make_uint4(Rbh[s*2].x, Rbh[s*2+1].x, Rbh[s*2].y, Rbh[s*2+1].y);
            if (TERMS == 2)
                *reinterpret_cast<uint4*>(&sm[buf][2][bword + off]) =
                    make_uint4(Rbl[s*2].x, Rbl[s*2+1].x, Rbl[s*2].y, Rbl[s*2+1].y);
        }
    };

    float acc[4][4][4];
#pragma unroll
    for (int mt = 0; mt < 4; mt++)
#pragma unroll
        for (int nt = 0; nt < 4; nt++)
#pragma unroll
            for (int q = 0; q < 4; q++) acc[mt][nt][q] = 0.f;

    const int NCH = K >> 5;

    loadR(0); storeR(0);
    loadR(1);
    __syncthreads();

    for (int c = 0; c < NCH; c++) {
        const int st = c & 1;
        if (c + 1 < NCH) storeR(st ^ 1);   // R holds chunk c+1
        if (c + 2 < NCH) loadR(c + 2);

#pragma unroll
        for (int s = 0; s < 2; s++) {
            const int off = s * 1024;
            // B-hi fragments
            uint32_t bh[4][2];
#pragma unroll
            for (int nt = 0; nt < 4; nt++) {
                const int bbase = (((wn >> 3) + nt) << 6) + lane * 2 + off;
                uint2 h2 = *reinterpret_cast<const uint2*>(&sm[st][1][bbase]);
                bh[nt][0] = h2.x; bh[nt][1] = h2.y;
            }
            // A fragments
            uint32_t af[4][4];
#pragma unroll
            for (int mt = 0; mt < 4; mt++) {
                const int abase = (((wm >> 4) + mt) << 7) + lane * 4 + off;
                uint4 h4 = *reinterpret_cast<const uint4*>(&sm[st][0][abase]);
                af[mt][0] = h4.x; af[mt][1] = h4.y; af[mt][2] = h4.z; af[mt][3] = h4.w;
            }
            // term 0: a * bh
#pragma unroll
            for (int mt = 0; mt < 4; mt++)
#pragma unroll
                for (int nt = 0; nt < 4; nt++)
                    mma_f16(acc[mt][nt], af[mt], bh[nt]);
            if (TERMS == 2) {
                // term 1: a * bl
                uint32_t bl[4][2];
#pragma unroll
                for (int nt = 0; nt < 4; nt++) {
                    const int bbase = (((wn >> 3) + nt) << 6) + lane * 2 + off;
                    uint2 l2 = *reinterpret_cast<const uint2*>(&sm[st][2][bbase]);
                    bl[nt][0] = l2.x; bl[nt][1] = l2.y;
                }
#pragma unroll
                for (int mt = 0; mt < 4; mt++)
#pragma unroll
                    for (int nt = 0; nt < 4; nt++)
                        mma_f16(acc[mt][nt], af[mt], bl[nt]);
            }
        }

        if (c + 1 < NCH) __syncthreads();
    }

    // ---- epilogue ----
#pragma unroll
    for (int mt = 0; mt < 4; mt++) {
        const int r0 = bm + wm + mt * 16 + g;
#pragma unroll
        for (int nt = 0; nt < 4; nt++) {
            const int c0 = bn + wn + nt * 8 + 2 * tg;
            float2 v0 = make_float2(acc[mt][nt][0], acc[mt][nt][1]);   // row r0
            float2 v1 = make_float2(acc[mt][nt][2], acc[mt][nt][3]);   // row r0+8
            if (EPI == 0 || EPI == 2) {
                if (EPI == 2) {
                    const float* mk = E + (size_t)bz * e_s;
                    const float q0 = (1.f - mk[c0])     * -10000.f;
                    const float q1 = (1.f - mk[c0 + 1]) * -10000.f;
                    v0.x = v0.x * scale + q0;  v0.y = v0.y * scale + q1;
                    v1.x = v1.x * scale + q0;  v1.y = v1.y * scale + q1;
                }
                float* Cb = Cf + (size_t)bz * c_bs;
                *reinterpret_cast<float2*>(Cb + (size_t)r0 * c_ld + c0)       = v0;
                *reinterpret_cast<float2*>(Cb + (size_t)(r0 + 8) * c_ld + c0) = v1;
            } else {
                // EPI 3: +bias[m]; EPI 4: +bias[n]; fp16 single out
                if (EPI == 3) {
                    v0.x += E[r0];     v0.y += E[r0];
                    v1.x += E[r0 + 8]; v1.y += E[r0 + 8];
                } else {
                    v0.x += E[c0]; v0.y += E[c0 + 1];
                    v1.x += E[c0]; v1.y += E[c0 + 1];
                }
                *reinterpret_cast<__half2*>(Ch + (size_t)r0 * c_ld + c0) =
                    __halves2half2(__float2half_rn(v0.x), __float2half_rn(v0.y));
                *reinterpret_cast<__half2*>(Ch + (size_t)(r0 + 8) * c_ld + c0) =
                    __halves2half2(__float2half_rn(v1.x), __float2half_rn(v1.y));
            }
        }
    }
}

// ---------------------------------------------------------------------------
// Pre-pass: fp32 -> fp16 single convert (one float4 per thread)
// ---------------------------------------------------------------------------
__global__ __launch_bounds__(256)
void cvt_kern(const float* __restrict__ X, __half* __restrict__ H, int n4)
{
    int i = blockIdx.x * blockDim.x + threadIdx.x;
    if (i >= n4) return;
    float4 v = reinterpret_cast<const float4*>(X)[i];
    cvt4h(H, (size_t)i * 4, v);
}

// ---------------------------------------------------------------------------
// Pre-pass: weight transpose + split (pair) or convert (single).
// ---------------------------------------------------------------------------
template<bool PAIR>
__global__ __launch_bounds__(256)
void tsplit_kern(const float* __restrict__ W, __half* __restrict__ TH,
                 __half* __restrict__ TL)
{
    __shared__ float t[32][33];
    const int bx = blockIdx.x * 32;   // n
    const int by = blockIdx.y * 32;   // k
    const int x = threadIdx.x & 31;
    const int y = threadIdx.x >> 5;
#pragma unroll
    for (int i = 0; i < 4; i++)
        t[y + 8 * i][x] = W[(size_t)(by + y + 8 * i) * HID + bx + x];
    __syncthreads();
#pragma unroll
    for (int i = 0; i < 4; i++) {
        const int n = bx + y + 8 * i, k = by + x;
        if (PAIR) {
            __half h, l;
            split2h(t[x][y + 8 * i], h, l);
            TH[(size_t)n * HID + k] = h;
            TL[(size_t)n * HID + k] = l;
        } else {
            TH[(size_t)n * HID + k] = __float2half_rn(t[x][y + 8 * i]);
        }
    }
}

// ---------------------------------------------------------------------------
// Row softmax over N=2048; reads fp32 scores, writes fp16 single probs.
// ---------------------------------------------------------------------------
__device__ __forceinline__ float warp_max(float v) {
#pragma unroll
    for (int o = 16; o; o >>= 1) v = fmaxf(v, __shfl_xor_sync(0xFFFFFFFFu, v, o));
    return v;
}
__device__ __forceinline__ float warp_sum(float v) {
#pragma unroll
    for (int o = 16; o; o >>= 1) v += __shfl_xor_sync(0xFFFFFFFFu, v, o);
    return v;
}

__global__ __launch_bounds__(256)
void softmax_kern(const float* __restrict__ S, __half* __restrict__ P)
{
    const size_t row = blockIdx.x;
    const float* p = S + row * (size_t)SKV;
    const int tid = threadIdx.x;

    float4 v0 = *reinterpret_cast<const float4*>(p + tid * 4);
    float4 v1 = *reinterpret_cast<const float4*>(p + 1024 + tid * 4);

    float m = fmaxf(fmaxf(fmaxf(v0.x, v0.y), fmaxf(v0.z, v0.w)),
                    fmaxf(fmaxf(v1.x, v1.y), fmaxf(v1.z, v1.w)));

    __shared__ float red[8];
    float wm = warp_max(m);
    if ((tid & 31) == 0) red[tid >> 5] = wm;
    __syncthreads();
    float bm = red[0];
#pragma unroll
    for (int i = 1; i < 8; i++) bm = fmaxf(bm, red[i]);
    __syncthreads();

    v0.x = expf(v0.x - bm); v0.y = expf(v0.y - bm);
    v0.z = expf(v0.z - bm); v0.w = expf(v0.w - bm);
    v1.x = expf(v1.x - bm); v1.y = expf(v1.y - bm);
    v1.z = expf(v1.z - bm); v1.w = expf(v1.w - bm);

    float s = v0.x + v0.y + v0.z + v0.w + v1.x + v1.y + v1.z + v1.w;
    float ws = warp_sum(s);
    if ((tid & 31) == 0) red[tid >> 5] = ws;
    __syncthreads();
    float bs = 0.f;
#pragma unroll
    for (int i = 0; i < 8; i++) bs += red[i];

    const float inv = 1.f / bs;
    v0.x *= inv; v0.y *= inv; v0.z *= inv; v0.w *= inv;
    v1.x *= inv; v1.y *= inv; v1.z *= inv; v1.w *= inv;

    cvt4h(P, row * (size_t)SKV + tid * 4, v0);
    cvt4h(P, row * (size_t)SKV + 1024 + tid * 4, v1);
}

// ---------------------------------------------------------------------------
// Launch
// ---------------------------------------------------------------------------
extern "C" void kernel_launch(void* const* d_in, const int* in_sizes, int n_in,
                              void* d_out, int out_size)
{
    const float* Xq   = (const float*)d_in[0];
    const float* Xk   = (const float*)d_in[1];
    const float* mask = (const float*)d_in[2];
    const float* Wq   = (const float*)d_in[3];
    const float* bq   = (const float*)d_in[4];
    const float* Wk   = (const float*)d_in[5];
    const float* bk   = (const float*)d_in[6];
    const float* Wv   = (const float*)d_in[7];
    const float* bv   = (const float*)d_in[8];
    float* out = (float*)d_out;

    __half *Xq1, *Xk1, *Wqth, *Wqtl, *Wkth, *Wktl, *Wvt;
    __half *Q1, *K1, *Vt, *Sp;
    float* S;
    cudaGetSymbolAddress((void**)&Xq1, gXq1);
    cudaGetSymbolAddress((void**)&Xk1, gXk1);
    cudaGetSymbolAddress((void**)&Wqth, gWqth); cudaGetSymbolAddress((void**)&Wqtl, gWqtl);
    cudaGetSymbolAddress((void**)&Wkth, gWkth); cudaGetSymbolAddress((void**)&Wktl, gWktl);
    cudaGetSymbolAddress((void**)&Wvt, gWvt);
    cudaGetSymbolAddress((void**)&Q1, gQ1);
    cudaGetSymbolAddress((void**)&K1, gK1);
    cudaGetSymbolAddress((void**)&Vt, gVt);
    cudaGetSymbolAddress((void**)&S, gS);
    cudaGetSymbolAddress((void**)&Sp, gSp);

    const float scale = 1.f / 32.f;   // 1/sqrt(1024)
    const int n4 = (int)(NX / 4);

    // Pre-pass: convert inputs to single fp16; weights Wq/Wk pair, Wv single
    cvt_kern<<<(n4 + 255) / 256, 256>>>(Xq, Xq1, n4);
    cvt_kern<<<(n4 + 255) / 256, 256>>>(Xk, Xk1, n4);
    tsplit_kern<true ><<<dim3(32, 32), 256>>>(Wq, Wqth, Wqtl);
    tsplit_kern<true ><<<dim3(32, 32), 256>>>(Wk, Wkth, Wktl);
    tsplit_kern<false><<<dim3(32, 32), 256>>>(Wv, Wvt, nullptr);

    // Q = Xq @ Wq + bq  (2-term: Xq single x Wq pair; single out)
    gemm_f16<2, 4><<<dim3(HID / 128, (BATCH * SQ) / 128, 1), 256>>>(
        Xq1, 0, HID, Wqth, Wqtl, 0, HID,
        nullptr, Q1, 0, HID, bq, 0, 1.f, HID);
    // K = Xk @ Wk + bk  (2-term; single out)
    gemm_f16<2, 4><<<dim3(HID / 128, (BATCH * SQ) / 128, 1), 256>>>(
        Xk1, 0, HID, Wkth, Wktl, 0, HID,
        nullptr, K1, 0, HID, bk, 0, 1.f, HID);
    // Vt = (Xk @ Wv + bv)^T  (1-term: Wvt single x Xk single; single out, bias[m])
    gemm_f16<1, 3><<<dim3((BATCH * SKV) / 128, HID / 128, 1), 256>>>(
        Wvt, 0, HID, Xk1, nullptr, 0, HID,
        nullptr, Vt, 0, BATCH * SKV, bv, 0, 1.f, HID);
    // S = Q @ K^T * scale + mask  (1-term: Q single x K single; fp32 out)
    gemm_f16<1, 2><<<dim3(SKV / 128, SQ / 128, BATCH), 256>>>(
        Q1, (size_t)SQ * HID, HID, K1, nullptr, (size_t)SKV * HID, HID,
        S, nullptr, (size_t)SQ * SKV, SKV, mask, SKV, scale, HID);
    // softmax -> fp16 single probs
    softmax_kern<<<BATCH * SQ, 256>>>(S, Sp);
    // out = P @ V  (1-term)
    gemm_f16<1, 0><<<dim3(HID / 128, SQ / 128, BATCH), 256>>>(
        Sp, (size_t)SQ * SKV, SKV, Vt, nullptr, (size_t)SKV, BATCH * SKV,
        out, nullptr, (size_t)SQ * HID, HID, nullptr, 0, 1.f, SKV);
}